// round 14
// baseline (speedup 1.0000x reference)
#include <cuda_runtime.h>
#include <cuda_fp16.h>
#include <mma.h>
#include <cstdint>

using namespace nvcuda;

#define B_SZ   16384
#define DIN    2048
#define XHAT_OFF (16384L*3)
#define SCAL_OFF (16384L*3 + 16384L*2048)

// k1: M=128 tile, K-chunk 64, single-pass fp16
#define TS2 72                        // fp16 smem row stride (144B; conflict-free)
#define STAGE_H1 (128*TS2)            // halves per array per stage (9216)
#define K1_SMEM (2*2*STAGE_H1*2)      // 2 stages x (Ah,Bh) = 73728 B

// k3 (champion): M=128 one-shot layout; mid region = stage scratch
#define TS3 136                       // fp16 row stride (272B)
#define K3_T (128*TS3)                // halves per array
#define K3_SMEM (3*K3_T*2)            // 104448 B -> 2 CTAs/SM
#define K3_XB_OFF (2*K3_T*2)          // X double buffer over Bh region (post-MMA)

// ---------------- scratch (device globals) ----------------
__device__ float g_prea[B_SZ*128];
__device__ float g_pred[B_SZ*128];
__device__ __align__(256) __half g_h3h[B_SZ*128];
__device__ __align__(256) __half g_d3h[B_SZ*128];
__device__ __align__(256) __half g_eW1h[128*2048];
__device__ __align__(256) __half g_dW4h[2048*128];
__device__ float g_part_po[512], g_part_tr[512], g_part_sz[512];
__device__ float g_part_rec[2048], g_part_sx[2048];

__device__ __forceinline__ unsigned pkh(__half a, __half b) {
    __half2 t = __halves2half2(a, b);
    return *reinterpret_cast<unsigned*>(&t);
}
__device__ __forceinline__ void cpa16(void* sdst, const void* gsrc) {
    unsigned s = (unsigned)__cvta_generic_to_shared(sdst);
    asm volatile("cp.async.cg.shared.global [%0], [%1], 16;\n" :: "r"(s), "l"(gsrc));
}
__device__ __forceinline__ void cp_commit() { asm volatile("cp.async.commit_group;\n"); }
__device__ __forceinline__ void cp_wait1() { asm volatile("cp.async.wait_group 1;\n"); }
__device__ __forceinline__ void cp_wait0() { asm volatile("cp.async.wait_group 0;\n"); }

// ================= K0 =================
__global__ void __launch_bounds__(256) k0_prep(const float* __restrict__ eW1,
                                               const float* __restrict__ dW4) {
    int i = blockIdx.x * 256 + threadIdx.x;
    if (i < 128*2048) {
        int n = i >> 11, k = i & 2047;
        g_eW1h[i] = __float2half(eW1[n*2049 + k]);
    }
    if (i < 2048*128) {
        g_dW4h[i] = __float2half(dW4[i]);
    }
}

// ================= K1: GEMM (M=16384, N=128, K=2048) fp16, chunk=64, pipelined ====
__global__ void __launch_bounds__(256, 2) k1_gemm(
    const float* __restrict__ x, const float* __restrict__ x_dot)
{
    extern __shared__ __half smb[];
    const int path = blockIdx.y;
    const float* A = (path == 0) ? x : x_dot;
    float* Out = (path == 0) ? g_prea : g_pred;
    const int m0 = blockIdx.x * 128;
    const int tid = threadIdx.x;
    const int w  = tid >> 5;
    const int wr = w >> 2;
    const int wc = w & 3;

    const float4* Asrc = reinterpret_cast<const float4*>(A);
    const uint4*  Bhg  = reinterpret_cast<const uint4*>(g_eW1h);

    const int ar  = tid >> 1;        // row 0..127
    const int ac8 = (tid & 1) * 8;   // float4 base within 64-float chunk
    const int br  = tid >> 1;
    const int bq0 = (tid & 1) * 4;   // uint4 base within 8-uint4 chunk row

    wmma::fragment<wmma::accumulator,16,16,16,float> acc[4][2];
    #pragma unroll
    for (int i=0;i<4;i++)
        #pragma unroll
        for(int j=0;j<2;j++) wmma::fill_fragment(acc[i][j], 0.0f);

    float4 areg[8];
    // ---- prologue: chunk 0 ----
    #pragma unroll
    for (int i=0;i<8;i++)
        areg[i] = Asrc[(long)(m0 + ar)*512 + ac8 + i];
    {
        __half* Bh = smb + STAGE_H1;
        #pragma unroll
        for (int qq=0;qq<4;qq++)
            cpa16(&Bh[br*TS2 + (bq0+qq)*8], &Bhg[br*256 + bq0 + qq]);
        cp_commit();
        __half* Ah = smb;
        #pragma unroll
        for (int i=0;i<8;i++) {
            float4 v = areg[i];
            unsigned* ph = reinterpret_cast<unsigned*>(&Ah[ar*TS2 + (ac8+i)*4]);
            ph[0]=pkh(__float2half(v.x), __float2half(v.y));
            ph[1]=pkh(__float2half(v.z), __float2half(v.w));
        }
    }

    #pragma unroll 1
    for (int c = 0; c < 32; c++) {
        const int s  = c & 1;
        const int sn = s ^ 1;
        if (c < 31) {
            #pragma unroll
            for (int i=0;i<8;i++)
                areg[i] = Asrc[(long)(m0 + ar)*512 + (c+1)*16 + ac8 + i];
            __half* Bh = smb + sn*2*STAGE_H1 + STAGE_H1;
            #pragma unroll
            for (int qq=0;qq<4;qq++)
                cpa16(&Bh[br*TS2 + (bq0+qq)*8], &Bhg[br*256 + (c+1)*8 + bq0 + qq]);
            cp_commit();
            cp_wait1();
        } else {
            cp_wait0();
        }
        __syncthreads();
        {
            __half* Ah = smb + s*2*STAGE_H1;
            __half* Bh = Ah + STAGE_H1;
            #pragma unroll
            for (int kk = 0; kk < 64; kk += 16) {
                wmma::fragment<wmma::matrix_b,16,16,16,__half,wmma::col_major> bh[2];
                #pragma unroll
                for (int j=0;j<2;j++)
                    wmma::load_matrix_sync(bh[j], &Bh[(wc*32 + j*16)*TS2 + kk], TS2);
                #pragma unroll
                for (int i=0;i<4;i++) {
                    wmma::fragment<wmma::matrix_a,16,16,16,__half,wmma::row_major> ah;
                    wmma::load_matrix_sync(ah, &Ah[(wr*64 + i*16)*TS2 + kk], TS2);
                    #pragma unroll
                    for (int j=0;j<2;j++)
                        wmma::mma_sync(acc[i][j], ah, bh[j], acc[i][j]);
                }
            }
        }
        if (c < 31) {
            __syncthreads();
            __half* Ah = smb + sn*2*STAGE_H1;
            #pragma unroll
            for (int i=0;i<8;i++) {
                float4 v = areg[i];
                unsigned* ph = reinterpret_cast<unsigned*>(&Ah[ar*TS2 + (ac8+i)*4]);
                ph[0]=pkh(__float2half(v.x), __float2half(v.y));
                ph[1]=pkh(__float2half(v.z), __float2half(v.w));
            }
        }
    }
    #pragma unroll
    for (int i=0;i<4;i++)
        #pragma unroll
        for (int j=0;j<2;j++) {
            float* p = Out + (long)(m0 + wr*64 + i*16)*128 + wc*32 + j*16;
            wmma::store_matrix_sync(p, acc[i][j], 128, wmma::mem_row_major);
        }
}

// ================= K2: fused middle chain (float2-packed activation buffers) ====
#define W2T_OFF   0
#define W3T_OFF   (W2T_OFF + 128*64)
#define W4S_OFF   (W3T_OFF + 64*32)
#define DW1T_OFF  (W4S_OFF + 96)
#define DW2T_OFF  (DW1T_OFF + 96)
#define DW3T_OFF  (DW2T_OFF + 32*64)
#define EB1_OFF   (DW3T_OFF + 64*128)
#define EB2_OFF   (EB1_OFF + 128)
#define EB3_OFF   (EB2_OFF + 64)
#define EB4_OFF   (EB3_OFF + 32)
#define DB1_OFF   (EB4_OFF + 4)
#define DB2_OFF   (DB1_OFF + 32)
#define DB3_OFF   (DB2_OFF + 64)
#define W1L_OFF   (DB3_OFF + 128)
#define COEF_OFF  (W1L_OFF + 128)
#define BUF_OFF   (COEF_OFF + 26)
#define LRED_OFF  (BUF_OFF + 8*256)
#define K2_FLOATS (LRED_OFF + 24)
#define K2_SMEM   (K2_FLOATS * 4)

__device__ __forceinline__ float sigf(float x) { return 1.f/(1.f+__expf(-x)); }

__global__ void __launch_bounds__(256) k2_chain(
    const float* __restrict__ treatment, const float* __restrict__ size_,
    const float* __restrict__ eW1, const float* __restrict__ eb1,
    const float* __restrict__ eW2, const float* __restrict__ eb2,
    const float* __restrict__ eW3, const float* __restrict__ eb3,
    const float* __restrict__ eW4, const float* __restrict__ eb4,
    const float* __restrict__ dW1, const float* __restrict__ db1,
    const float* __restrict__ dW2, const float* __restrict__ db2,
    const float* __restrict__ dW3, const float* __restrict__ db3,
    const float* __restrict__ coef,
    float* __restrict__ out)
{
    extern __shared__ float sm[];
    const int tid = threadIdx.x;

    for (int i = tid; i < 64*128; i += 256) { int n=i>>7, k=i&127; sm[W2T_OFF + k*64 + n] = eW2[i]; }
    for (int i = tid; i < 32*64;  i += 256) { int n=i>>6, k=i&63;  sm[W3T_OFF + k*32 + n] = eW3[i]; }
    for (int i = tid; i < 3*32;   i += 256) sm[W4S_OFF + i] = eW4[i];
    for (int i = tid; i < 32*3;   i += 256) { int n=i/3,  k=i%3;  sm[DW1T_OFF + k*32 + n] = dW1[i]; }
    for (int i = tid; i < 64*32;  i += 256) { int n=i>>5, k=i&31; sm[DW2T_OFF + k*64 + n] = dW2[i]; }
    for (int i = tid; i < 128*64; i += 256) { int n=i>>6, k=i&63; sm[DW3T_OFF + k*128 + n] = dW3[i]; }
    if (tid < 128) sm[EB1_OFF+tid] = eb1[tid];
    if (tid < 64)  sm[EB2_OFF+tid] = eb2[tid];
    if (tid < 32)  sm[EB3_OFF+tid] = eb3[tid];
    if (tid < 3)   sm[EB4_OFF+tid] = eb4[tid];
    if (tid < 32)  sm[DB1_OFF+tid] = db1[tid];
    if (tid < 64)  sm[DB2_OFF+tid] = db2[tid];
    if (tid < 128) sm[DB3_OFF+tid] = db3[tid];
    if (tid < 128) sm[W1L_OFF+tid] = eW1[tid*2049 + 2048];
    if (tid < 21)  sm[COEF_OFF+tid] = coef[tid];
    __syncthreads();

    const int w = tid >> 5, lane = tid & 31;
    float2* pbuf = reinterpret_cast<float2*>(sm + BUF_OFF + w*256);
    float po = 0.f, tr = 0.f, szl = 0.f;

    for (int rr = 0; rr < 4; rr++) {
        const int row = (blockIdx.x*8 + w)*4 + rr;
        const float tre = treatment[row];

        #pragma unroll
        for (int jj=0;jj<4;jj++) {
            int n = lane + 32*jj;
            float add = tre * sm[W1L_OFF+n];
            float a1  = sigf(g_prea[(long)row*128+n] + add + sm[EB1_OFF+n]);
            float pd  = g_pred[(long)row*128+n] + add;
            pbuf[n] = make_float2(a1, a1*(1.f-a1)*pd);
        }
        __syncwarp();
        float a2v[2], d2v[2];
        #pragma unroll
        for (int jj=0;jj<2;jj++) {
            int n = lane + 32*jj;
            float s1 = sm[EB2_OFF+n], s2 = 0.f;
            #pragma unroll 8
            for (int k=0;k<128;k++) {
                float wv = sm[W2T_OFF + k*64 + n];
                float2 ad = pbuf[k];
                s1 = fmaf(ad.x, wv, s1);
                s2 = fmaf(ad.y, wv, s2);
            }
            float a = sigf(s1);
            a2v[jj] = a; d2v[jj] = a*(1.f-a)*s2;
        }
        __syncwarp();
        pbuf[lane]    = make_float2(a2v[0], d2v[0]);
        pbuf[lane+32] = make_float2(a2v[1], d2v[1]);
        __syncwarp();
        {
            float s1 = sm[EB3_OFF+lane], s2 = 0.f;
            #pragma unroll 8
            for (int k=0;k<64;k++) {
                float wv = sm[W3T_OFF + k*32 + lane];
                float2 ad = pbuf[k];
                s1 = fmaf(ad.x, wv, s1);
                s2 = fmaf(ad.y, wv, s2);
            }
            float a = sigf(s1);
            float d = a*(1.f-a)*s2;
            __syncwarp();
            pbuf[lane] = make_float2(a, d);
        }
        __syncwarp();
        float zz[3], zt[3];
        #pragma unroll
        for (int j=0;j<3;j++) {
            float s1 = sm[EB4_OFF+j], s2 = 0.f;
            #pragma unroll
            for (int k=0;k<32;k++) {
                float wv = sm[W4S_OFF + j*32 + k];
                float2 ad = pbuf[k];
                s1 = fmaf(ad.x, wv, s1);
                s2 = fmaf(ad.y, wv, s2);
            }
            zz[j]=s1; zt[j]=s2;
        }
        const float s = zz[0], d = zz[1], t3 = zz[2];
        float th[7] = {1.f, s, s*s, s*d, s*t3, s*s*d, s*s*t3};
        float zp[3] = {0.f,0.f,0.f};
        #pragma unroll
        for (int i=0;i<7;i++) {
            zp[0] = fmaf(th[i], sm[COEF_OFF+i*3+0], zp[0]);
            zp[1] = fmaf(th[i], sm[COEF_OFF+i*3+1], zp[1]);
            zp[2] = fmaf(th[i], sm[COEF_OFF+i*3+2], zp[2]);
        }
        if (lane == 0) {
            float dpo = s - size_[row];
            po += dpo*dpo;
            float l = t3;
            tr += fmaxf(l, 0.f) + log1pf(expf(-fabsf(l))) - l*tre;
            float e0 = zt[0]-zp[0], e1 = zt[1]-zp[1], e2 = zt[2]-zp[2];
            szl += e0*e0 + e1*e1 + e2*e2;
        }
        if (lane < 3) out[(long)row*3 + lane] = zz[lane];
        __syncwarp();
        {
            float w0 = sm[DW1T_OFF + 0*32 + lane];
            float w1 = sm[DW1T_OFF + 1*32 + lane];
            float w2 = sm[DW1T_OFF + 2*32 + lane];
            float h  = sigf(sm[DB1_OFF+lane] + s*w0 + d*w1 + t3*w2);
            float pd = zp[0]*w0 + zp[1]*w1 + zp[2]*w2;
            pbuf[lane] = make_float2(h, h*(1.f-h)*pd);
        }
        __syncwarp();
        float h2v[2], dd2v[2];
        #pragma unroll
        for (int jj=0;jj<2;jj++) {
            int n = lane + 32*jj;
            float s1 = sm[DB2_OFF+n], s2 = 0.f;
            #pragma unroll
            for (int k=0;k<32;k++) {
                float wv = sm[DW2T_OFF + k*64 + n];
                float2 ad = pbuf[k];
                s1 = fmaf(ad.x, wv, s1);
                s2 = fmaf(ad.y, wv, s2);
            }
            float h = sigf(s1);
            h2v[jj]=h; dd2v[jj]=h*(1.f-h)*s2;
        }
        __syncwarp();
        pbuf[lane]    = make_float2(h2v[0], dd2v[0]);
        pbuf[lane+32] = make_float2(h2v[1], dd2v[1]);
        __syncwarp();
        #pragma unroll
        for (int jj=0;jj<4;jj++) {
            int n = lane + 32*jj;
            float s1 = sm[DB3_OFF+n], s2 = 0.f;
            #pragma unroll 8
            for (int k=0;k<64;k++) {
                float wv = sm[DW3T_OFF + k*128 + n];
                float2 ad = pbuf[k];
                s1 = fmaf(ad.x, wv, s1);
                s2 = fmaf(ad.y, wv, s2);
            }
            float h = sigf(s1);
            float hd = h*(1.f-h)*s2;
            long idx = (long)row*128 + n;
            g_h3h[idx] = __float2half(h);
            g_d3h[idx] = __float2half(hd);
        }
        __syncwarp();
    }
    if (lane == 0) {
        sm[LRED_OFF + w]      = po;
        sm[LRED_OFF + 8 + w]  = tr;
        sm[LRED_OFF + 16 + w] = szl;
    }
    __syncthreads();
    if (tid == 0) {
        float a=0.f,b=0.f,c=0.f;
        for (int i=0;i<8;i++){ a+=sm[LRED_OFF+i]; b+=sm[LRED_OFF+8+i]; c+=sm[LRED_OFF+16+i]; }
        g_part_po[blockIdx.x]=a; g_part_tr[blockIdx.x]=b; g_part_sz[blockIdx.x]=c;
    }
}

// ================= K3 (champion): 1-pass one-shot GEMM + prefetched epilogue ====
__global__ void __launch_bounds__(256, 2) k3_gemm(
    const float* __restrict__ db4,
    const float* __restrict__ x, const float* __restrict__ x_dot,
    float* __restrict__ out)
{
    extern __shared__ __half smb[];
    char* smc = reinterpret_cast<char*>(smb);
    __half* Ah = smb;
    __half* Bh = smb + 2*K3_T;
    float* stgf = reinterpret_cast<float*>(smb);
    float* XB[2] = { reinterpret_cast<float*>(smc + K3_XB_OFF),
                     reinterpret_cast<float*>(smc + K3_XB_OFF + 16384) };

    const int path = blockIdx.z;
    const __half* Asrc = (path == 0) ? g_h3h : g_d3h;
    const float* Xs = (path == 0) ? x : x_dot;
    const int m0 = blockIdx.y * 128;
    const int n0 = blockIdx.x * 128;
    const int tid = threadIdx.x;
    const int w  = tid >> 5;
    const int lane = tid & 31;
    const int wr = w >> 2;
    const int wc = w & 3;

    {
        const uint4* Ah4 = reinterpret_cast<const uint4*>(Asrc + (long)m0*128);
        const uint4* Bh4 = reinterpret_cast<const uint4*>(g_dW4h + (long)n0*128);
        const int r  = tid >> 1;
        const int q0 = (tid & 1) * 8;
        #pragma unroll
        for (int qq = 0; qq < 8; qq++) {
            int q = q0 + qq;
            cpa16(&Ah[r*TS3 + q*8], &Ah4[r*16 + q]);
            cpa16(&Bh[r*TS3 + q*8], &Bh4[r*16 + q]);
        }
        cp_commit(); cp_wait0();
    }
    __syncthreads();

    wmma::fragment<wmma::accumulator,16,16,16,float> acc[4][2];
    #pragma unroll
    for (int i=0;i<4;i++)
        #pragma unroll
        for(int j=0;j<2;j++) wmma::fill_fragment(acc[i][j], 0.0f);

    #pragma unroll
    for (int kk = 0; kk < 128; kk += 16) {
        wmma::fragment<wmma::matrix_b,16,16,16,__half,wmma::col_major> bh[2];
        #pragma unroll
        for (int j=0;j<2;j++)
            wmma::load_matrix_sync(bh[j], &Bh[(wc*32 + j*16)*TS3 + kk], TS3);
        #pragma unroll
        for (int i=0;i<4;i++) {
            wmma::fragment<wmma::matrix_a,16,16,16,__half,wmma::row_major> ah;
            wmma::load_matrix_sync(ah, &Ah[(wr*64 + i*16)*TS3 + kk], TS3);
            #pragma unroll
            for (int j=0;j<2;j++)
                wmma::mma_sync(acc[i][j], ah, bh[j], acc[i][j]);
        }
    }
    __syncthreads();

    {
        const int r = tid >> 3, q = tid & 7;
        #pragma unroll
        for (int ii = 0; ii < 4; ii++) {
            int rr = r + 32*ii;
            cpa16(&XB[0][rr*32 + q*4], &Xs[(long)(m0+rr)*2048 + n0 + 0*32 + q*4]);
        }
        cp_commit();
        #pragma unroll
        for (int i=0;i<4;i++)
            #pragma unroll
            for (int j=0;j<2;j++)
                wmma::store_matrix_sync(&stgf[(wr*64 + i*16)*132 + wc*32 + j*16],
                                        acc[i][j], 132, wmma::mem_row_major);
        #pragma unroll
        for (int ii = 0; ii < 4; ii++) {
            int rr = r + 32*ii;
            cpa16(&XB[1][rr*32 + q*4], &Xs[(long)(m0+rr)*2048 + n0 + 1*32 + q*4]);
        }
        cp_commit();
    }

    float lacc = 0.f;
    #pragma unroll 1
    for (int ch = 0; ch < 4; ch++) {
        if (ch < 3) cp_wait1(); else cp_wait0();
        __syncthreads();
        const float* xb = XB[ch & 1];
        const int cg = n0 + ch*32 + lane;
        const float db4v = (path == 0) ? db4[cg] : 0.f;
        #pragma unroll
        for (int i = 0; i < 16; i++) {
            int rloc = w*16 + i;
            float v = stgf[rloc*132 + ch*32 + lane];
            if (path == 0) {
                v += db4v;
                out[XHAT_OFF + (long)(m0+rloc)*2048 + cg] = v;
            }
            float df = v - xb[rloc*32 + lane];
            lacc += df*df;
        }
        if (ch < 2) {
            __syncthreads();
            const int r = tid >> 3, q = tid & 7;
            #pragma unroll
            for (int ii = 0; ii < 4; ii++) {
                int rr = r + 32*ii;
                cpa16(&XB[ch & 1][rr*32 + q*4],
                      &Xs[(long)(m0+rr)*2048 + n0 + (ch+2)*32 + q*4]);
            }
            cp_commit();
        }
    }

    __shared__ float wred[8];
    #pragma unroll
    for (int o = 16; o > 0; o >>= 1) lacc += __shfl_down_sync(0xffffffffu, lacc, o);
    if (lane == 0) wred[w] = lacc;
    __syncthreads();
    if (tid == 0) {
        float t = 0.f;
        #pragma unroll
        for (int i=0;i<8;i++) t += wred[i];
        int idx = blockIdx.y*16 + blockIdx.x;
        if (path == 0) g_part_rec[idx] = t;
        else           g_part_sx[idx]  = t;
    }
}

// ================= K4: deterministic finalize =================
__global__ void k4_final(const float* __restrict__ coef, float* __restrict__ out) {
    const int w = threadIdx.x >> 5, lane = threadIdx.x & 31;
    float s = 0.f;
    if      (w == 0) { for (int i=lane;i<512;i+=32)  s += g_part_po[i]; }
    else if (w == 1) { for (int i=lane;i<512;i+=32)  s += g_part_tr[i]; }
    else if (w == 2) { for (int i=lane;i<512;i+=32)  s += g_part_sz[i]; }
    else if (w == 3) { for (int i=lane;i<2048;i+=32) s += g_part_rec[i]; }
    else if (w == 4) { for (int i=lane;i<2048;i+=32) s += g_part_sx[i]; }
    else             { for (int i=lane;i<21;i+=32)   s += fabsf(coef[i]); }
    #pragma unroll
    for (int o=16;o>0;o>>=1) s += __shfl_down_sync(0xffffffffu, s, o);
    if (lane == 0) {
        if      (w == 0) out[SCAL_OFF+0] = s / 16384.f;
        else if (w == 1) out[SCAL_OFF+1] = s / 16384.f;
        else if (w == 2) out[SCAL_OFF+4] = s / (16384.f*3.f);
        else if (w == 3) out[SCAL_OFF+2] = s / (16384.f*2048.f);
        else if (w == 4) out[SCAL_OFF+3] = s / (16384.f*2048.f);
        else             out[SCAL_OFF+5] = s / 21.f;
    }
}

// ================= launch =================
extern "C" void kernel_launch(void* const* d_in, const int* in_sizes, int n_in,
                              void* d_out, int out_size) {
    const float* x         = (const float*)d_in[0];
    const float* x_dot     = (const float*)d_in[1];
    const float* treatment = (const float*)d_in[2];
    const float* size_     = (const float*)d_in[3];
    const float* eW1 = (const float*)d_in[4];  const float* eb1 = (const float*)d_in[5];
    const float* eW2 = (const float*)d_in[6];  const float* eb2 = (const float*)d_in[7];
    const float* eW3 = (const float*)d_in[8];  const float* eb3 = (const float*)d_in[9];
    const float* eW4 = (const float*)d_in[10]; const float* eb4 = (const float*)d_in[11];
    const float* dW1 = (const float*)d_in[12]; const float* db1 = (const float*)d_in[13];
    const float* dW2 = (const float*)d_in[14]; const float* db2 = (const float*)d_in[15];
    const float* dW3 = (const float*)d_in[16]; const float* db3 = (const float*)d_in[17];
    const float* dW4 = (const float*)d_in[18]; const float* db4 = (const float*)d_in[19];
    const float* coef = (const float*)d_in[20];
    float* out = (float*)d_out;

    cudaFuncSetAttribute(k1_gemm, cudaFuncAttributeMaxDynamicSharedMemorySize, K1_SMEM);
    cudaFuncSetAttribute(k3_gemm, cudaFuncAttributeMaxDynamicSharedMemorySize, K3_SMEM);
    cudaFuncSetAttribute(k2_chain, cudaFuncAttributeMaxDynamicSharedMemorySize, K2_SMEM);

    k0_prep<<<1024, 256>>>(eW1, dW4);
    k1_gemm<<<dim3(128, 2), 256, K1_SMEM>>>(x, x_dot);
    k2_chain<<<512, 256, K2_SMEM>>>(treatment, size_, eW1, eb1, eW2, eb2, eW3, eb3,
                                    eW4, eb4, dW1, db1, dW2, db2, dW3, db3, coef, out);
    k3_gemm<<<dim3(16, 128, 2), 256, K3_SMEM>>>(db4, x, x_dot, out);
    k4_final<<<1, 192>>>(coef, out);
}

// round 15
// speedup vs baseline: 1.1552x; 1.1552x over previous
#include <cuda_runtime.h>
#include <cuda_fp16.h>
#include <mma.h>
#include <cstdint>

using namespace nvcuda;

#define B_SZ   16384
#define DIN    2048
#define XHAT_OFF (16384L*3)
#define SCAL_OFF (16384L*3 + 16384L*2048)

// k1 (champion R11): M=128 tile, single-pass fp16 (Ah, Bh only)
#define TS2 40                       // fp16 smem row stride (80B)
#define STAGE_H (128*TS2)
#define K1_SMEM (2*2*STAGE_H*2)      // 40960 B

// k3 (champion): M=128 one-shot layout; mid region = stage scratch
#define TS3 136                      // fp16 row stride (272B)
#define K3_T (128*TS3)               // halves per array
#define K3_SMEM (3*K3_T*2)           // 104448 B -> 2 CTAs/SM
#define K3_XB_OFF (2*K3_T*2)         // X double buffer over Bh region (post-MMA)

// ---------------- scratch (device globals) ----------------
__device__ float g_prea[B_SZ*128];
__device__ float g_pred[B_SZ*128];
__device__ __align__(256) __half g_h3h[B_SZ*128];
__device__ __align__(256) __half g_d3h[B_SZ*128];
__device__ __align__(256) __half g_eW1h[128*2048];
__device__ __align__(256) __half g_dW4h[2048*128];
__device__ float g_part_po[512], g_part_tr[512], g_part_sz[512];
__device__ float g_part_rec[2048], g_part_sx[2048];

__device__ __forceinline__ unsigned pkh(__half a, __half b) {
    __half2 t = __halves2half2(a, b);
    return *reinterpret_cast<unsigned*>(&t);
}
__device__ __forceinline__ void cpa16(void* sdst, const void* gsrc) {
    unsigned s = (unsigned)__cvta_generic_to_shared(sdst);
    asm volatile("cp.async.cg.shared.global [%0], [%1], 16;\n" :: "r"(s), "l"(gsrc));
}
__device__ __forceinline__ void cp_commit() { asm volatile("cp.async.commit_group;\n"); }
__device__ __forceinline__ void cp_wait1() { asm volatile("cp.async.wait_group 1;\n"); }
__device__ __forceinline__ void cp_wait0() { asm volatile("cp.async.wait_group 0;\n"); }

// ================= K0 =================
__global__ void __launch_bounds__(256) k0_prep(const float* __restrict__ eW1,
                                               const float* __restrict__ dW4) {
    int i = blockIdx.x * 256 + threadIdx.x;
    if (i < 128*2048) {
        int n = i >> 11, k = i & 2047;
        g_eW1h[i] = __float2half(eW1[n*2049 + k]);
    }
    if (i < 2048*128) {
        g_dW4h[i] = __float2half(dW4[i]);
    }
}

// ================= K1 (champion R11): GEMM fp16 1-pass, pipelined ====
__global__ void __launch_bounds__(256, 2) k1_gemm(
    const float* __restrict__ x, const float* __restrict__ x_dot)
{
    extern __shared__ __half smb[];
    const int path = blockIdx.y;
    const float* A = (path == 0) ? x : x_dot;
    float* Out = (path == 0) ? g_prea : g_pred;
    const int m0 = blockIdx.x * 128;
    const int tid = threadIdx.x;
    const int w  = tid >> 5;
    const int wr = w >> 2;
    const int wc = w & 3;

    const float4* Asrc = reinterpret_cast<const float4*>(A);
    const uint4*  Bhg  = reinterpret_cast<const uint4*>(g_eW1h);

    const int ar  = tid >> 3;
    const int ac4 = tid & 7;
    const int br  = tid >> 2;
    const int bgc = tid & 3;

    wmma::fragment<wmma::accumulator,16,16,16,float> acc[4][2];
    #pragma unroll
    for (int i=0;i<4;i++)
        #pragma unroll
        for(int j=0;j<2;j++) wmma::fill_fragment(acc[i][j], 0.0f);

    float4 areg[4];
    #pragma unroll
    for (int i=0;i<4;i++)
        areg[i] = Asrc[(long)(m0 + ar + 32*i)*512 + ac4];
    {
        __half* Bh = smb + STAGE_H;
        #pragma unroll
        for (int i=0;i<2;i++) {
            int r = br + 64*i;
            cpa16(&Bh[r*TS2 + bgc*8], &Bhg[r*256 + bgc]);
        }
        cp_commit();
        __half* Ah = smb;
        #pragma unroll
        for (int i=0;i<4;i++) {
            int r = ar + 32*i;
            float4 v = areg[i];
            unsigned* ph = reinterpret_cast<unsigned*>(&Ah[r*TS2 + ac4*4]);
            ph[0]=pkh(__float2half(v.x), __float2half(v.y));
            ph[1]=pkh(__float2half(v.z), __float2half(v.w));
        }
    }

    #pragma unroll 1
    for (int c = 0; c < 64; c++) {
        const int s  = c & 1;
        const int sn = s ^ 1;
        if (c < 63) {
            #pragma unroll
            for (int i=0;i<4;i++)
                areg[i] = Asrc[(long)(m0 + ar + 32*i)*512 + (c+1)*8 + ac4];
            __half* Bh = smb + sn*2*STAGE_H + STAGE_H;
            #pragma unroll
            for (int i=0;i<2;i++) {
                int r = br + 64*i;
                cpa16(&Bh[r*TS2 + bgc*8], &Bhg[r*256 + (c+1)*4 + bgc]);
            }
            cp_commit();
            cp_wait1();
        } else {
            cp_wait0();
        }
        __syncthreads();
        {
            __half* Ah = smb + s*2*STAGE_H;
            __half* Bh = Ah + STAGE_H;
            #pragma unroll
            for (int kk = 0; kk < 32; kk += 16) {
                wmma::fragment<wmma::matrix_b,16,16,16,__half,wmma::col_major> bh[2];
                #pragma unroll
                for (int j=0;j<2;j++)
                    wmma::load_matrix_sync(bh[j], &Bh[(wc*32 + j*16)*TS2 + kk], TS2);
                #pragma unroll
                for (int i=0;i<4;i++) {
                    wmma::fragment<wmma::matrix_a,16,16,16,__half,wmma::row_major> ah;
                    wmma::load_matrix_sync(ah, &Ah[(wr*64 + i*16)*TS2 + kk], TS2);
                    #pragma unroll
                    for (int j=0;j<2;j++)
                        wmma::mma_sync(acc[i][j], ah, bh[j], acc[i][j]);
                }
            }
        }
        if (c < 63) {
            __syncthreads();
            __half* Ah = smb + sn*2*STAGE_H;
            #pragma unroll
            for (int i=0;i<4;i++) {
                int r = ar + 32*i;
                float4 v = areg[i];
                unsigned* ph = reinterpret_cast<unsigned*>(&Ah[r*TS2 + ac4*4]);
                ph[0]=pkh(__float2half(v.x), __float2half(v.y));
                ph[1]=pkh(__float2half(v.z), __float2half(v.w));
            }
        }
    }
    #pragma unroll
    for (int i=0;i<4;i++)
        #pragma unroll
        for (int j=0;j<2;j++) {
            float* p = Out + (long)(m0 + wr*64 + i*16)*128 + wc*32 + j*16;
            wmma::store_matrix_sync(p, acc[i][j], 128, wmma::mem_row_major);
        }
}

// ================= K2: fused middle chain (float2-packed activation buffers) ====
#define W2T_OFF   0
#define W3T_OFF   (W2T_OFF + 128*64)
#define W4S_OFF   (W3T_OFF + 64*32)
#define DW1T_OFF  (W4S_OFF + 96)
#define DW2T_OFF  (DW1T_OFF + 96)
#define DW3T_OFF  (DW2T_OFF + 32*64)
#define EB1_OFF   (DW3T_OFF + 64*128)
#define EB2_OFF   (EB1_OFF + 128)
#define EB3_OFF   (EB2_OFF + 64)
#define EB4_OFF   (EB3_OFF + 32)
#define DB1_OFF   (EB4_OFF + 4)
#define DB2_OFF   (DB1_OFF + 32)
#define DB3_OFF   (DB2_OFF + 64)
#define W1L_OFF   (DB3_OFF + 128)
#define COEF_OFF  (W1L_OFF + 128)
#define BUF_OFF   (COEF_OFF + 26)
#define LRED_OFF  (BUF_OFF + 8*256)
#define K2_FLOATS (LRED_OFF + 24)
#define K2_SMEM   (K2_FLOATS * 4)

__device__ __forceinline__ float sigf(float x) { return 1.f/(1.f+__expf(-x)); }

__global__ void __launch_bounds__(256) k2_chain(
    const float* __restrict__ treatment, const float* __restrict__ size_,
    const float* __restrict__ eW1, const float* __restrict__ eb1,
    const float* __restrict__ eW2, const float* __restrict__ eb2,
    const float* __restrict__ eW3, const float* __restrict__ eb3,
    const float* __restrict__ eW4, const float* __restrict__ eb4,
    const float* __restrict__ dW1, const float* __restrict__ db1,
    const float* __restrict__ dW2, const float* __restrict__ db2,
    const float* __restrict__ dW3, const float* __restrict__ db3,
    const float* __restrict__ coef,
    float* __restrict__ out)
{
    extern __shared__ float sm[];
    const int tid = threadIdx.x;

    for (int i = tid; i < 64*128; i += 256) { int n=i>>7, k=i&127; sm[W2T_OFF + k*64 + n] = eW2[i]; }
    for (int i = tid; i < 32*64;  i += 256) { int n=i>>6, k=i&63;  sm[W3T_OFF + k*32 + n] = eW3[i]; }
    for (int i = tid; i < 3*32;   i += 256) sm[W4S_OFF + i] = eW4[i];
    for (int i = tid; i < 32*3;   i += 256) { int n=i/3,  k=i%3;  sm[DW1T_OFF + k*32 + n] = dW1[i]; }
    for (int i = tid; i < 64*32;  i += 256) { int n=i>>5, k=i&31; sm[DW2T_OFF + k*64 + n] = dW2[i]; }
    for (int i = tid; i < 128*64; i += 256) { int n=i>>6, k=i&63; sm[DW3T_OFF + k*128 + n] = dW3[i]; }
    if (tid < 128) sm[EB1_OFF+tid] = eb1[tid];
    if (tid < 64)  sm[EB2_OFF+tid] = eb2[tid];
    if (tid < 32)  sm[EB3_OFF+tid] = eb3[tid];
    if (tid < 3)   sm[EB4_OFF+tid] = eb4[tid];
    if (tid < 32)  sm[DB1_OFF+tid] = db1[tid];
    if (tid < 64)  sm[DB2_OFF+tid] = db2[tid];
    if (tid < 128) sm[DB3_OFF+tid] = db3[tid];
    if (tid < 128) sm[W1L_OFF+tid] = eW1[tid*2049 + 2048];
    if (tid < 21)  sm[COEF_OFF+tid] = coef[tid];
    __syncthreads();

    const int w = tid >> 5, lane = tid & 31;
    float2* pbuf = reinterpret_cast<float2*>(sm + BUF_OFF + w*256);
    float po = 0.f, tr = 0.f, szl = 0.f;

    for (int rr = 0; rr < 4; rr++) {
        const int row = (blockIdx.x*8 + w)*4 + rr;
        const float tre = treatment[row];

        #pragma unroll
        for (int jj=0;jj<4;jj++) {
            int n = lane + 32*jj;
            float add = tre * sm[W1L_OFF+n];
            float a1  = sigf(g_prea[(long)row*128+n] + add + sm[EB1_OFF+n]);
            float pd  = g_pred[(long)row*128+n] + add;
            pbuf[n] = make_float2(a1, a1*(1.f-a1)*pd);
        }
        __syncwarp();
        float a2v[2], d2v[2];
        #pragma unroll
        for (int jj=0;jj<2;jj++) {
            int n = lane + 32*jj;
            float s1 = sm[EB2_OFF+n], s2 = 0.f;
            #pragma unroll 8
            for (int k=0;k<128;k++) {
                float wv = sm[W2T_OFF + k*64 + n];
                float2 ad = pbuf[k];
                s1 = fmaf(ad.x, wv, s1);
                s2 = fmaf(ad.y, wv, s2);
            }
            float a = sigf(s1);
            a2v[jj] = a; d2v[jj] = a*(1.f-a)*s2;
        }
        __syncwarp();
        pbuf[lane]    = make_float2(a2v[0], d2v[0]);
        pbuf[lane+32] = make_float2(a2v[1], d2v[1]);
        __syncwarp();
        {
            float s1 = sm[EB3_OFF+lane], s2 = 0.f;
            #pragma unroll 8
            for (int k=0;k<64;k++) {
                float wv = sm[W3T_OFF + k*32 + lane];
                float2 ad = pbuf[k];
                s1 = fmaf(ad.x, wv, s1);
                s2 = fmaf(ad.y, wv, s2);
            }
            float a = sigf(s1);
            float d = a*(1.f-a)*s2;
            __syncwarp();
            pbuf[lane] = make_float2(a, d);
        }
        __syncwarp();
        float zz[3], zt[3];
        #pragma unroll
        for (int j=0;j<3;j++) {
            float s1 = sm[EB4_OFF+j], s2 = 0.f;
            #pragma unroll
            for (int k=0;k<32;k++) {
                float wv = sm[W4S_OFF + j*32 + k];
                float2 ad = pbuf[k];
                s1 = fmaf(ad.x, wv, s1);
                s2 = fmaf(ad.y, wv, s2);
            }
            zz[j]=s1; zt[j]=s2;
        }
        const float s = zz[0], d = zz[1], t3 = zz[2];
        float th[7] = {1.f, s, s*s, s*d, s*t3, s*s*d, s*s*t3};
        float zp[3] = {0.f,0.f,0.f};
        #pragma unroll
        for (int i=0;i<7;i++) {
            zp[0] = fmaf(th[i], sm[COEF_OFF+i*3+0], zp[0]);
            zp[1] = fmaf(th[i], sm[COEF_OFF+i*3+1], zp[1]);
            zp[2] = fmaf(th[i], sm[COEF_OFF+i*3+2], zp[2]);
        }
        if (lane == 0) {
            float dpo = s - size_[row];
            po += dpo*dpo;
            float l = t3;
            tr += fmaxf(l, 0.f) + log1pf(expf(-fabsf(l))) - l*tre;
            float e0 = zt[0]-zp[0], e1 = zt[1]-zp[1], e2 = zt[2]-zp[2];
            szl += e0*e0 + e1*e1 + e2*e2;
        }
        if (lane < 3) out[(long)row*3 + lane] = zz[lane];
        __syncwarp();
        {
            float w0 = sm[DW1T_OFF + 0*32 + lane];
            float w1 = sm[DW1T_OFF + 1*32 + lane];
            float w2 = sm[DW1T_OFF + 2*32 + lane];
            float h  = sigf(sm[DB1_OFF+lane] + s*w0 + d*w1 + t3*w2);
            float pd = zp[0]*w0 + zp[1]*w1 + zp[2]*w2;
            pbuf[lane] = make_float2(h, h*(1.f-h)*pd);
        }
        __syncwarp();
        float h2v[2], dd2v[2];
        #pragma unroll
        for (int jj=0;jj<2;jj++) {
            int n = lane + 32*jj;
            float s1 = sm[DB2_OFF+n], s2 = 0.f;
            #pragma unroll
            for (int k=0;k<32;k++) {
                float wv = sm[DW2T_OFF + k*64 + n];
                float2 ad = pbuf[k];
                s1 = fmaf(ad.x, wv, s1);
                s2 = fmaf(ad.y, wv, s2);
            }
            float h = sigf(s1);
            h2v[jj]=h; dd2v[jj]=h*(1.f-h)*s2;
        }
        __syncwarp();
        pbuf[lane]    = make_float2(h2v[0], dd2v[0]);
        pbuf[lane+32] = make_float2(h2v[1], dd2v[1]);
        __syncwarp();
        #pragma unroll
        for (int jj=0;jj<4;jj++) {
            int n = lane + 32*jj;
            float s1 = sm[DB3_OFF+n], s2 = 0.f;
            #pragma unroll 8
            for (int k=0;k<64;k++) {
                float wv = sm[DW3T_OFF + k*128 + n];
                float2 ad = pbuf[k];
                s1 = fmaf(ad.x, wv, s1);
                s2 = fmaf(ad.y, wv, s2);
            }
            float h = sigf(s1);
            float hd = h*(1.f-h)*s2;
            long idx = (long)row*128 + n;
            g_h3h[idx] = __float2half(h);
            g_d3h[idx] = __float2half(hd);
        }
        __syncwarp();
    }
    if (lane == 0) {
        sm[LRED_OFF + w]      = po;
        sm[LRED_OFF + 8 + w]  = tr;
        sm[LRED_OFF + 16 + w] = szl;
    }
    __syncthreads();
    if (tid == 0) {
        float a=0.f,b=0.f,c=0.f;
        for (int i=0;i<8;i++){ a+=sm[LRED_OFF+i]; b+=sm[LRED_OFF+8+i]; c+=sm[LRED_OFF+16+i]; }
        g_part_po[blockIdx.x]=a; g_part_tr[blockIdx.x]=b; g_part_sz[blockIdx.x]=c;
    }
}

// ================= K3 (champion): 1-pass one-shot GEMM + prefetched epilogue ====
__global__ void __launch_bounds__(256, 2) k3_gemm(
    const float* __restrict__ db4,
    const float* __restrict__ x, const float* __restrict__ x_dot,
    float* __restrict__ out)
{
    extern __shared__ __half smb[];
    char* smc = reinterpret_cast<char*>(smb);
    __half* Ah = smb;
    __half* Bh = smb + 2*K3_T;
    float* stgf = reinterpret_cast<float*>(smb);
    float* XB[2] = { reinterpret_cast<float*>(smc + K3_XB_OFF),
                     reinterpret_cast<float*>(smc + K3_XB_OFF + 16384) };

    const int path = blockIdx.z;
    const __half* Asrc = (path == 0) ? g_h3h : g_d3h;
    const float* Xs = (path == 0) ? x : x_dot;
    const int m0 = blockIdx.y * 128;
    const int n0 = blockIdx.x * 128;
    const int tid = threadIdx.x;
    const int w  = tid >> 5;
    const int lane = tid & 31;
    const int wr = w >> 2;
    const int wc = w & 3;

    {
        const uint4* Ah4 = reinterpret_cast<const uint4*>(Asrc + (long)m0*128);
        const uint4* Bh4 = reinterpret_cast<const uint4*>(g_dW4h + (long)n0*128);
        const int r  = tid >> 1;
        const int q0 = (tid & 1) * 8;
        #pragma unroll
        for (int qq = 0; qq < 8; qq++) {
            int q = q0 + qq;
            cpa16(&Ah[r*TS3 + q*8], &Ah4[r*16 + q]);
            cpa16(&Bh[r*TS3 + q*8], &Bh4[r*16 + q]);
        }
        cp_commit(); cp_wait0();
    }
    __syncthreads();

    wmma::fragment<wmma::accumulator,16,16,16,float> acc[4][2];
    #pragma unroll
    for (int i=0;i<4;i++)
        #pragma unroll
        for(int j=0;j<2;j++) wmma::fill_fragment(acc[i][j], 0.0f);

    #pragma unroll
    for (int kk = 0; kk < 128; kk += 16) {
        wmma::fragment<wmma::matrix_b,16,16,16,__half,wmma::col_major> bh[2];
        #pragma unroll
        for (int j=0;j<2;j++)
            wmma::load_matrix_sync(bh[j], &Bh[(wc*32 + j*16)*TS3 + kk], TS3);
        #pragma unroll
        for (int i=0;i<4;i++) {
            wmma::fragment<wmma::matrix_a,16,16,16,__half,wmma::row_major> ah;
            wmma::load_matrix_sync(ah, &Ah[(wr*64 + i*16)*TS3 + kk], TS3);
            #pragma unroll
            for (int j=0;j<2;j++)
                wmma::mma_sync(acc[i][j], ah, bh[j], acc[i][j]);
        }
    }
    __syncthreads();

    {
        const int r = tid >> 3, q = tid & 7;
        #pragma unroll
        for (int ii = 0; ii < 4; ii++) {
            int rr = r + 32*ii;
            cpa16(&XB[0][rr*32 + q*4], &Xs[(long)(m0+rr)*2048 + n0 + 0*32 + q*4]);
        }
        cp_commit();
        #pragma unroll
        for (int i=0;i<4;i++)
            #pragma unroll
            for (int j=0;j<2;j++)
                wmma::store_matrix_sync(&stgf[(wr*64 + i*16)*132 + wc*32 + j*16],
                                        acc[i][j], 132, wmma::mem_row_major);
        #pragma unroll
        for (int ii = 0; ii < 4; ii++) {
            int rr = r + 32*ii;
            cpa16(&XB[1][rr*32 + q*4], &Xs[(long)(m0+rr)*2048 + n0 + 1*32 + q*4]);
        }
        cp_commit();
    }

    float lacc = 0.f;
    #pragma unroll 1
    for (int ch = 0; ch < 4; ch++) {
        if (ch < 3) cp_wait1(); else cp_wait0();
        __syncthreads();
        const float* xb = XB[ch & 1];
        const int cg = n0 + ch*32 + lane;
        const float db4v = (path == 0) ? db4[cg] : 0.f;
        #pragma unroll
        for (int i = 0; i < 16; i++) {
            int rloc = w*16 + i;
            float v = stgf[rloc*132 + ch*32 + lane];
            if (path == 0) {
                v += db4v;
                out[XHAT_OFF + (long)(m0+rloc)*2048 + cg] = v;
            }
            float df = v - xb[rloc*32 + lane];
            lacc += df*df;
        }
        if (ch < 2) {
            __syncthreads();
            const int r = tid >> 3, q = tid & 7;
            #pragma unroll
            for (int ii = 0; ii < 4; ii++) {
                int rr = r + 32*ii;
                cpa16(&XB[ch & 1][rr*32 + q*4],
                      &Xs[(long)(m0+rr)*2048 + n0 + (ch+2)*32 + q*4]);
            }
            cp_commit();
        }
    }

    __shared__ float wred[8];
    #pragma unroll
    for (int o = 16; o > 0; o >>= 1) lacc += __shfl_down_sync(0xffffffffu, lacc, o);
    if (lane == 0) wred[w] = lacc;
    __syncthreads();
    if (tid == 0) {
        float t = 0.f;
        #pragma unroll
        for (int i=0;i<8;i++) t += wred[i];
        int idx = blockIdx.y*16 + blockIdx.x;
        if (path == 0) g_part_rec[idx] = t;
        else           g_part_sx[idx]  = t;
    }
}

// ================= K4: parallel deterministic finalize (512 threads) ==========
__global__ void __launch_bounds__(512) k4_final(const float* __restrict__ coef,
                                                float* __restrict__ out) {
    __shared__ float part[6][16];
    const int tid = threadIdx.x, w = tid >> 5, lane = tid & 31;
    float v[6];
    v[0] = g_part_po[tid];
    v[1] = g_part_tr[tid];
    v[2] = g_part_sz[tid];
    v[3] = g_part_rec[tid] + g_part_rec[tid+512] + g_part_rec[tid+1024] + g_part_rec[tid+1536];
    v[4] = g_part_sx[tid]  + g_part_sx[tid+512]  + g_part_sx[tid+1024]  + g_part_sx[tid+1536];
    v[5] = (tid < 21) ? fabsf(coef[tid]) : 0.f;
    #pragma unroll
    for (int j = 0; j < 6; j++) {
        float s = v[j];
        #pragma unroll
        for (int o = 16; o > 0; o >>= 1) s += __shfl_down_sync(0xffffffffu, s, o);
        if (lane == 0) part[j][w] = s;
    }
    __syncthreads();
    if (w < 6) {
        float s = (lane < 16) ? part[w][lane] : 0.f;
        #pragma unroll
        for (int o = 8; o > 0; o >>= 1) s += __shfl_down_sync(0xffffffffu, s, o);
        if (lane == 0) {
            if      (w == 0) out[SCAL_OFF+0] = s / 16384.f;                 // loss_po
            else if (w == 1) out[SCAL_OFF+1] = s / 16384.f;                 // loss_tr
            else if (w == 2) out[SCAL_OFF+4] = s / (16384.f*3.f);           // sindy_z
            else if (w == 3) out[SCAL_OFF+2] = s / (16384.f*2048.f);        // recon
            else if (w == 4) out[SCAL_OFF+3] = s / (16384.f*2048.f);        // sindy_x
            else             out[SCAL_OFF+5] = s / 21.f;                    // l1
        }
    }
}

// ================= launch =================
extern "C" void kernel_launch(void* const* d_in, const int* in_sizes, int n_in,
                              void* d_out, int out_size) {
    const float* x         = (const float*)d_in[0];
    const float* x_dot     = (const float*)d_in[1];
    const float* treatment = (const float*)d_in[2];
    const float* size_     = (const float*)d_in[3];
    const float* eW1 = (const float*)d_in[4];  const float* eb1 = (const float*)d_in[5];
    const float* eW2 = (const float*)d_in[6];  const float* eb2 = (const float*)d_in[7];
    const float* eW3 = (const float*)d_in[8];  const float* eb3 = (const float*)d_in[9];
    const float* eW4 = (const float*)d_in[10]; const float* eb4 = (const float*)d_in[11];
    const float* dW1 = (const float*)d_in[12]; const float* db1 = (const float*)d_in[13];
    const float* dW2 = (const float*)d_in[14]; const float* db2 = (const float*)d_in[15];
    const float* dW3 = (const float*)d_in[16]; const float* db3 = (const float*)d_in[17];
    const float* dW4 = (const float*)d_in[18]; const float* db4 = (const float*)d_in[19];
    const float* coef = (const float*)d_in[20];
    float* out = (float*)d_out;

    cudaFuncSetAttribute(k1_gemm, cudaFuncAttributeMaxDynamicSharedMemorySize, K1_SMEM);
    cudaFuncSetAttribute(k3_gemm, cudaFuncAttributeMaxDynamicSharedMemorySize, K3_SMEM);
    cudaFuncSetAttribute(k2_chain, cudaFuncAttributeMaxDynamicSharedMemorySize, K2_SMEM);

    k0_prep<<<1024, 256>>>(eW1, dW4);
    k1_gemm<<<dim3(128, 2), 256, K1_SMEM>>>(x, x_dot);
    k2_chain<<<512, 256, K2_SMEM>>>(treatment, size_, eW1, eb1, eW2, eb2, eW3, eb3,
                                    eW4, eb4, dW1, db1, dW2, db2, dW3, db3, coef, out);
    k3_gemm<<<dim3(16, 128, 2), 256, K3_SMEM>>>(db4, x, x_dot, out);
    k4_final<<<1, 512>>>(coef, out);
}

// round 16
// speedup vs baseline: 1.2211x; 1.0571x over previous
#include <cuda_runtime.h>
#include <cuda_fp16.h>
#include <mma.h>
#include <cstdint>

using namespace nvcuda;

#define B_SZ   16384
#define DIN    2048
#define XHAT_OFF (16384L*3)
#define SCAL_OFF (16384L*3 + 16384L*2048)

// k1 (champion R11): M=128 tile, single-pass fp16 (Ah, Bh only)
#define TS2 40                       // fp16 smem row stride (80B)
#define STAGE_H (128*TS2)
#define K1_SMEM (2*2*STAGE_H*2)      // 40960 B

// k3 (champion): M=128 one-shot layout; mid region = stage scratch
#define TS3 136                      // fp16 row stride (272B)
#define K3_T (128*TS3)               // halves per array
#define K3_SMEM (3*K3_T*2)           // 104448 B -> 2 CTAs/SM
#define K3_XB_OFF (2*K3_T*2)         // X double buffer over Bh region (post-MMA)

// ---------------- scratch (device globals) ----------------
__device__ float g_prea[B_SZ*128];
__device__ float g_pred[B_SZ*128];
__device__ __align__(256) __half g_h3h[B_SZ*128];
__device__ __align__(256) __half g_d3h[B_SZ*128];
__device__ __align__(256) __half g_eW1h[128*2048];
__device__ __align__(256) __half g_dW4h[2048*128];
__device__ float g_part_po[256], g_part_tr[256], g_part_sz[256];
__device__ float g_part_rec[2048], g_part_sx[2048];

__device__ __forceinline__ unsigned pkh(__half a, __half b) {
    __half2 t = __halves2half2(a, b);
    return *reinterpret_cast<unsigned*>(&t);
}
__device__ __forceinline__ void cpa16(void* sdst, const void* gsrc) {
    unsigned s = (unsigned)__cvta_generic_to_shared(sdst);
    asm volatile("cp.async.cg.shared.global [%0], [%1], 16;\n" :: "r"(s), "l"(gsrc));
}
__device__ __forceinline__ void cp_commit() { asm volatile("cp.async.commit_group;\n"); }
__device__ __forceinline__ void cp_wait1() { asm volatile("cp.async.wait_group 1;\n"); }
__device__ __forceinline__ void cp_wait0() { asm volatile("cp.async.wait_group 0;\n"); }

// ================= K0 =================
__global__ void __launch_bounds__(256) k0_prep(const float* __restrict__ eW1,
                                               const float* __restrict__ dW4) {
    int i = blockIdx.x * 256 + threadIdx.x;
    if (i < 128*2048) {
        int n = i >> 11, k = i & 2047;
        g_eW1h[i] = __float2half(eW1[n*2049 + k]);
    }
    if (i < 2048*128) {
        g_dW4h[i] = __float2half(dW4[i]);
    }
}

// ================= K1 (champion R11): GEMM fp16 1-pass, pipelined ====
__global__ void __launch_bounds__(256, 2) k1_gemm(
    const float* __restrict__ x, const float* __restrict__ x_dot)
{
    extern __shared__ __half smb[];
    const int path = blockIdx.y;
    const float* A = (path == 0) ? x : x_dot;
    float* Out = (path == 0) ? g_prea : g_pred;
    const int m0 = blockIdx.x * 128;
    const int tid = threadIdx.x;
    const int w  = tid >> 5;
    const int wr = w >> 2;
    const int wc = w & 3;

    const float4* Asrc = reinterpret_cast<const float4*>(A);
    const uint4*  Bhg  = reinterpret_cast<const uint4*>(g_eW1h);

    const int ar  = tid >> 3;
    const int ac4 = tid & 7;
    const int br  = tid >> 2;
    const int bgc = tid & 3;

    wmma::fragment<wmma::accumulator,16,16,16,float> acc[4][2];
    #pragma unroll
    for (int i=0;i<4;i++)
        #pragma unroll
        for(int j=0;j<2;j++) wmma::fill_fragment(acc[i][j], 0.0f);

    float4 areg[4];
    #pragma unroll
    for (int i=0;i<4;i++)
        areg[i] = Asrc[(long)(m0 + ar + 32*i)*512 + ac4];
    {
        __half* Bh = smb + STAGE_H;
        #pragma unroll
        for (int i=0;i<2;i++) {
            int r = br + 64*i;
            cpa16(&Bh[r*TS2 + bgc*8], &Bhg[r*256 + bgc]);
        }
        cp_commit();
        __half* Ah = smb;
        #pragma unroll
        for (int i=0;i<4;i++) {
            int r = ar + 32*i;
            float4 v = areg[i];
            unsigned* ph = reinterpret_cast<unsigned*>(&Ah[r*TS2 + ac4*4]);
            ph[0]=pkh(__float2half(v.x), __float2half(v.y));
            ph[1]=pkh(__float2half(v.z), __float2half(v.w));
        }
    }

    #pragma unroll 1
    for (int c = 0; c < 64; c++) {
        const int s  = c & 1;
        const int sn = s ^ 1;
        if (c < 63) {
            #pragma unroll
            for (int i=0;i<4;i++)
                areg[i] = Asrc[(long)(m0 + ar + 32*i)*512 + (c+1)*8 + ac4];
            __half* Bh = smb + sn*2*STAGE_H + STAGE_H;
            #pragma unroll
            for (int i=0;i<2;i++) {
                int r = br + 64*i;
                cpa16(&Bh[r*TS2 + bgc*8], &Bhg[r*256 + (c+1)*4 + bgc]);
            }
            cp_commit();
            cp_wait1();
        } else {
            cp_wait0();
        }
        __syncthreads();
        {
            __half* Ah = smb + s*2*STAGE_H;
            __half* Bh = Ah + STAGE_H;
            #pragma unroll
            for (int kk = 0; kk < 32; kk += 16) {
                wmma::fragment<wmma::matrix_b,16,16,16,__half,wmma::col_major> bh[2];
                #pragma unroll
                for (int j=0;j<2;j++)
                    wmma::load_matrix_sync(bh[j], &Bh[(wc*32 + j*16)*TS2 + kk], TS2);
                #pragma unroll
                for (int i=0;i<4;i++) {
                    wmma::fragment<wmma::matrix_a,16,16,16,__half,wmma::row_major> ah;
                    wmma::load_matrix_sync(ah, &Ah[(wr*64 + i*16)*TS2 + kk], TS2);
                    #pragma unroll
                    for (int j=0;j<2;j++)
                        wmma::mma_sync(acc[i][j], ah, bh[j], acc[i][j]);
                }
            }
        }
        if (c < 63) {
            __syncthreads();
            __half* Ah = smb + sn*2*STAGE_H;
            #pragma unroll
            for (int i=0;i<4;i++) {
                int r = ar + 32*i;
                float4 v = areg[i];
                unsigned* ph = reinterpret_cast<unsigned*>(&Ah[r*TS2 + ac4*4]);
                ph[0]=pkh(__float2half(v.x), __float2half(v.y));
                ph[1]=pkh(__float2half(v.z), __float2half(v.w));
            }
        }
    }
    #pragma unroll
    for (int i=0;i<4;i++)
        #pragma unroll
        for (int j=0;j<2;j++) {
            float* p = Out + (long)(m0 + wr*64 + i*16)*128 + wc*32 + j*16;
            wmma::store_matrix_sync(p, acc[i][j], 128, wmma::mem_row_major);
        }
}

// ================= K2: fused middle chain, 64 rows/CTA, single wave =========
#define W2T_OFF   0
#define W3T_OFF   (W2T_OFF + 128*64)
#define W4S_OFF   (W3T_OFF + 64*32)
#define DW1T_OFF  (W4S_OFF + 96)
#define DW2T_OFF  (DW1T_OFF + 96)
#define DW3T_OFF  (DW2T_OFF + 32*64)
#define EB1_OFF   (DW3T_OFF + 64*128)
#define EB2_OFF   (EB1_OFF + 128)
#define EB3_OFF   (EB2_OFF + 64)
#define EB4_OFF   (EB3_OFF + 32)
#define DB1_OFF   (EB4_OFF + 4)
#define DB2_OFF   (DB1_OFF + 32)
#define DB3_OFF   (DB2_OFF + 64)
#define W1L_OFF   (DB3_OFF + 128)
#define COEF_OFF  (W1L_OFF + 128)
#define BUF_OFF   (COEF_OFF + 26)
#define LRED_OFF  (BUF_OFF + 8*256)
#define K2_FLOATS (LRED_OFF + 24)
#define K2_SMEM   (K2_FLOATS * 4)

__device__ __forceinline__ float sigf(float x) { return 1.f/(1.f+__expf(-x)); }

__global__ void __launch_bounds__(256) k2_chain(
    const float* __restrict__ treatment, const float* __restrict__ size_,
    const float* __restrict__ eW1, const float* __restrict__ eb1,
    const float* __restrict__ eW2, const float* __restrict__ eb2,
    const float* __restrict__ eW3, const float* __restrict__ eb3,
    const float* __restrict__ eW4, const float* __restrict__ eb4,
    const float* __restrict__ dW1, const float* __restrict__ db1,
    const float* __restrict__ dW2, const float* __restrict__ db2,
    const float* __restrict__ dW3, const float* __restrict__ db3,
    const float* __restrict__ coef,
    float* __restrict__ out)
{
    extern __shared__ float sm[];
    const int tid = threadIdx.x;

    for (int i = tid; i < 64*128; i += 256) { int n=i>>7, k=i&127; sm[W2T_OFF + k*64 + n] = eW2[i]; }
    for (int i = tid; i < 32*64;  i += 256) { int n=i>>6, k=i&63;  sm[W3T_OFF + k*32 + n] = eW3[i]; }
    for (int i = tid; i < 3*32;   i += 256) sm[W4S_OFF + i] = eW4[i];
    for (int i = tid; i < 32*3;   i += 256) { int n=i/3,  k=i%3;  sm[DW1T_OFF + k*32 + n] = dW1[i]; }
    for (int i = tid; i < 64*32;  i += 256) { int n=i>>5, k=i&31; sm[DW2T_OFF + k*64 + n] = dW2[i]; }
    for (int i = tid; i < 128*64; i += 256) { int n=i>>6, k=i&63; sm[DW3T_OFF + k*128 + n] = dW3[i]; }
    if (tid < 128) sm[EB1_OFF+tid] = eb1[tid];
    if (tid < 64)  sm[EB2_OFF+tid] = eb2[tid];
    if (tid < 32)  sm[EB3_OFF+tid] = eb3[tid];
    if (tid < 3)   sm[EB4_OFF+tid] = eb4[tid];
    if (tid < 32)  sm[DB1_OFF+tid] = db1[tid];
    if (tid < 64)  sm[DB2_OFF+tid] = db2[tid];
    if (tid < 128) sm[DB3_OFF+tid] = db3[tid];
    if (tid < 128) sm[W1L_OFF+tid] = eW1[tid*2049 + 2048];
    if (tid < 21)  sm[COEF_OFF+tid] = coef[tid];
    __syncthreads();

    const int w = tid >> 5, lane = tid & 31;
    float2* pbuf = reinterpret_cast<float2*>(sm + BUF_OFF + w*256);
    float po = 0.f, tr = 0.f, szl = 0.f;

    for (int rr = 0; rr < 8; rr++) {
        const int row = (blockIdx.x*8 + w)*8 + rr;
        const float tre = treatment[row];

        #pragma unroll
        for (int jj=0;jj<4;jj++) {
            int n = lane + 32*jj;
            float add = tre * sm[W1L_OFF+n];
            float a1  = sigf(g_prea[(long)row*128+n] + add + sm[EB1_OFF+n]);
            float pd  = g_pred[(long)row*128+n] + add;
            pbuf[n] = make_float2(a1, a1*(1.f-a1)*pd);
        }
        __syncwarp();
        float a2v[2], d2v[2];
        #pragma unroll
        for (int jj=0;jj<2;jj++) {
            int n = lane + 32*jj;
            float s1 = sm[EB2_OFF+n], s2 = 0.f;
            #pragma unroll 8
            for (int k=0;k<128;k++) {
                float wv = sm[W2T_OFF + k*64 + n];
                float2 ad = pbuf[k];
                s1 = fmaf(ad.x, wv, s1);
                s2 = fmaf(ad.y, wv, s2);
            }
            float a = sigf(s1);
            a2v[jj] = a; d2v[jj] = a*(1.f-a)*s2;
        }
        __syncwarp();
        pbuf[lane]    = make_float2(a2v[0], d2v[0]);
        pbuf[lane+32] = make_float2(a2v[1], d2v[1]);
        __syncwarp();
        {
            float s1 = sm[EB3_OFF+lane], s2 = 0.f;
            #pragma unroll 8
            for (int k=0;k<64;k++) {
                float wv = sm[W3T_OFF + k*32 + lane];
                float2 ad = pbuf[k];
                s1 = fmaf(ad.x, wv, s1);
                s2 = fmaf(ad.y, wv, s2);
            }
            float a = sigf(s1);
            float d = a*(1.f-a)*s2;
            __syncwarp();
            pbuf[lane] = make_float2(a, d);
        }
        __syncwarp();
        float zz[3], zt[3];
        #pragma unroll
        for (int j=0;j<3;j++) {
            float s1 = sm[EB4_OFF+j], s2 = 0.f;
            #pragma unroll
            for (int k=0;k<32;k++) {
                float wv = sm[W4S_OFF + j*32 + k];
                float2 ad = pbuf[k];
                s1 = fmaf(ad.x, wv, s1);
                s2 = fmaf(ad.y, wv, s2);
            }
            zz[j]=s1; zt[j]=s2;
        }
        const float s = zz[0], d = zz[1], t3 = zz[2];
        float th[7] = {1.f, s, s*s, s*d, s*t3, s*s*d, s*s*t3};
        float zp[3] = {0.f,0.f,0.f};
        #pragma unroll
        for (int i=0;i<7;i++) {
            zp[0] = fmaf(th[i], sm[COEF_OFF+i*3+0], zp[0]);
            zp[1] = fmaf(th[i], sm[COEF_OFF+i*3+1], zp[1]);
            zp[2] = fmaf(th[i], sm[COEF_OFF+i*3+2], zp[2]);
        }
        if (lane == 0) {
            float dpo = s - size_[row];
            po += dpo*dpo;
            float l = t3;
            tr += fmaxf(l, 0.f) + log1pf(expf(-fabsf(l))) - l*tre;
            float e0 = zt[0]-zp[0], e1 = zt[1]-zp[1], e2 = zt[2]-zp[2];
            szl += e0*e0 + e1*e1 + e2*e2;
        }
        if (lane < 3) out[(long)row*3 + lane] = zz[lane];
        __syncwarp();
        {
            float w0 = sm[DW1T_OFF + 0*32 + lane];
            float w1 = sm[DW1T_OFF + 1*32 + lane];
            float w2 = sm[DW1T_OFF + 2*32 + lane];
            float h  = sigf(sm[DB1_OFF+lane] + s*w0 + d*w1 + t3*w2);
            float pd = zp[0]*w0 + zp[1]*w1 + zp[2]*w2;
            pbuf[lane] = make_float2(h, h*(1.f-h)*pd);
        }
        __syncwarp();
        float h2v[2], dd2v[2];
        #pragma unroll
        for (int jj=0;jj<2;jj++) {
            int n = lane + 32*jj;
            float s1 = sm[DB2_OFF+n], s2 = 0.f;
            #pragma unroll
            for (int k=0;k<32;k++) {
                float wv = sm[DW2T_OFF + k*64 + n];
                float2 ad = pbuf[k];
                s1 = fmaf(ad.x, wv, s1);
                s2 = fmaf(ad.y, wv, s2);
            }
            float h = sigf(s1);
            h2v[jj]=h; dd2v[jj]=h*(1.f-h)*s2;
        }
        __syncwarp();
        pbuf[lane]    = make_float2(h2v[0], dd2v[0]);
        pbuf[lane+32] = make_float2(h2v[1], dd2v[1]);
        __syncwarp();
        #pragma unroll
        for (int jj=0;jj<4;jj++) {
            int n = lane + 32*jj;
            float s1 = sm[DB3_OFF+n], s2 = 0.f;
            #pragma unroll 8
            for (int k=0;k<64;k++) {
                float wv = sm[DW3T_OFF + k*128 + n];
                float2 ad = pbuf[k];
                s1 = fmaf(ad.x, wv, s1);
                s2 = fmaf(ad.y, wv, s2);
            }
            float h = sigf(s1);
            float hd = h*(1.f-h)*s2;
            long idx = (long)row*128 + n;
            g_h3h[idx] = __float2half(h);
            g_d3h[idx] = __float2half(hd);
        }
        __syncwarp();
    }
    if (lane == 0) {
        sm[LRED_OFF + w]      = po;
        sm[LRED_OFF + 8 + w]  = tr;
        sm[LRED_OFF + 16 + w] = szl;
    }
    __syncthreads();
    if (tid == 0) {
        float a=0.f,b=0.f,c=0.f;
        for (int i=0;i<8;i++){ a+=sm[LRED_OFF+i]; b+=sm[LRED_OFF+8+i]; c+=sm[LRED_OFF+16+i]; }
        g_part_po[blockIdx.x]=a; g_part_tr[blockIdx.x]=b; g_part_sz[blockIdx.x]=c;
    }
}

// ================= K3 (champion): 1-pass one-shot GEMM + prefetched epilogue ====
__global__ void __launch_bounds__(256, 2) k3_gemm(
    const float* __restrict__ db4,
    const float* __restrict__ x, const float* __restrict__ x_dot,
    float* __restrict__ out)
{
    extern __shared__ __half smb[];
    char* smc = reinterpret_cast<char*>(smb);
    __half* Ah = smb;
    __half* Bh = smb + 2*K3_T;
    float* stgf = reinterpret_cast<float*>(smb);
    float* XB[2] = { reinterpret_cast<float*>(smc + K3_XB_OFF),
                     reinterpret_cast<float*>(smc + K3_XB_OFF + 16384) };

    const int path = blockIdx.z;
    const __half* Asrc = (path == 0) ? g_h3h : g_d3h;
    const float* Xs = (path == 0) ? x : x_dot;
    const int m0 = blockIdx.y * 128;
    const int n0 = blockIdx.x * 128;
    const int tid = threadIdx.x;
    const int w  = tid >> 5;
    const int lane = tid & 31;
    const int wr = w >> 2;
    const int wc = w & 3;

    {
        const uint4* Ah4 = reinterpret_cast<const uint4*>(Asrc + (long)m0*128);
        const uint4* Bh4 = reinterpret_cast<const uint4*>(g_dW4h + (long)n0*128);
        const int r  = tid >> 1;
        const int q0 = (tid & 1) * 8;
        #pragma unroll
        for (int qq = 0; qq < 8; qq++) {
            int q = q0 + qq;
            cpa16(&Ah[r*TS3 + q*8], &Ah4[r*16 + q]);
            cpa16(&Bh[r*TS3 + q*8], &Bh4[r*16 + q]);
        }
        cp_commit(); cp_wait0();
    }
    __syncthreads();

    wmma::fragment<wmma::accumulator,16,16,16,float> acc[4][2];
    #pragma unroll
    for (int i=0;i<4;i++)
        #pragma unroll
        for(int j=0;j<2;j++) wmma::fill_fragment(acc[i][j], 0.0f);

    #pragma unroll
    for (int kk = 0; kk < 128; kk += 16) {
        wmma::fragment<wmma::matrix_b,16,16,16,__half,wmma::col_major> bh[2];
        #pragma unroll
        for (int j=0;j<2;j++)
            wmma::load_matrix_sync(bh[j], &Bh[(wc*32 + j*16)*TS3 + kk], TS3);
        #pragma unroll
        for (int i=0;i<4;i++) {
            wmma::fragment<wmma::matrix_a,16,16,16,__half,wmma::row_major> ah;
            wmma::load_matrix_sync(ah, &Ah[(wr*64 + i*16)*TS3 + kk], TS3);
            #pragma unroll
            for (int j=0;j<2;j++)
                wmma::mma_sync(acc[i][j], ah, bh[j], acc[i][j]);
        }
    }
    __syncthreads();

    {
        const int r = tid >> 3, q = tid & 7;
        #pragma unroll
        for (int ii = 0; ii < 4; ii++) {
            int rr = r + 32*ii;
            cpa16(&XB[0][rr*32 + q*4], &Xs[(long)(m0+rr)*2048 + n0 + 0*32 + q*4]);
        }
        cp_commit();
        #pragma unroll
        for (int i=0;i<4;i++)
            #pragma unroll
            for (int j=0;j<2;j++)
                wmma::store_matrix_sync(&stgf[(wr*64 + i*16)*132 + wc*32 + j*16],
                                        acc[i][j], 132, wmma::mem_row_major);
        #pragma unroll
        for (int ii = 0; ii < 4; ii++) {
            int rr = r + 32*ii;
            cpa16(&XB[1][rr*32 + q*4], &Xs[(long)(m0+rr)*2048 + n0 + 1*32 + q*4]);
        }
        cp_commit();
    }

    float lacc = 0.f;
    #pragma unroll 1
    for (int ch = 0; ch < 4; ch++) {
        if (ch < 3) cp_wait1(); else cp_wait0();
        __syncthreads();
        const float* xb = XB[ch & 1];
        const int cg = n0 + ch*32 + lane;
        const float db4v = (path == 0) ? db4[cg] : 0.f;
        #pragma unroll
        for (int i = 0; i < 16; i++) {
            int rloc = w*16 + i;
            float v = stgf[rloc*132 + ch*32 + lane];
            if (path == 0) {
                v += db4v;
                out[XHAT_OFF + (long)(m0+rloc)*2048 + cg] = v;
            }
            float df = v - xb[rloc*32 + lane];
            lacc += df*df;
        }
        if (ch < 2) {
            __syncthreads();
            const int r = tid >> 3, q = tid & 7;
            #pragma unroll
            for (int ii = 0; ii < 4; ii++) {
                int rr = r + 32*ii;
                cpa16(&XB[ch & 1][rr*32 + q*4],
                      &Xs[(long)(m0+rr)*2048 + n0 + (ch+2)*32 + q*4]);
            }
            cp_commit();
        }
    }

    __shared__ float wred[8];
    #pragma unroll
    for (int o = 16; o > 0; o >>= 1) lacc += __shfl_down_sync(0xffffffffu, lacc, o);
    if (lane == 0) wred[w] = lacc;
    __syncthreads();
    if (tid == 0) {
        float t = 0.f;
        #pragma unroll
        for (int i=0;i<8;i++) t += wred[i];
        int idx = blockIdx.y*16 + blockIdx.x;
        if (path == 0) g_part_rec[idx] = t;
        else           g_part_sx[idx]  = t;
    }
}

// ================= K4: parallel deterministic finalize (512 threads) ==========
__global__ void __launch_bounds__(512) k4_final(const float* __restrict__ coef,
                                                float* __restrict__ out) {
    __shared__ float part[6][16];
    const int tid = threadIdx.x, w = tid >> 5, lane = tid & 31;
    float v[6];
    v[0] = (tid < 256) ? g_part_po[tid] : 0.f;
    v[1] = (tid < 256) ? g_part_tr[tid] : 0.f;
    v[2] = (tid < 256) ? g_part_sz[tid] : 0.f;
    v[3] = g_part_rec[tid] + g_part_rec[tid+512] + g_part_rec[tid+1024] + g_part_rec[tid+1536];
    v[4] = g_part_sx[tid]  + g_part_sx[tid+512]  + g_part_sx[tid+1024]  + g_part_sx[tid+1536];
    v[5] = (tid < 21) ? fabsf(coef[tid]) : 0.f;
    #pragma unroll
    for (int j = 0; j < 6; j++) {
        float s = v[j];
        #pragma unroll
        for (int o = 16; o > 0; o >>= 1) s += __shfl_down_sync(0xffffffffu, s, o);
        if (lane == 0) part[j][w] = s;
    }
    __syncthreads();
    if (w < 6) {
        float s = (lane < 16) ? part[w][lane] : 0.f;
        #pragma unroll
        for (int o = 8; o > 0; o >>= 1) s += __shfl_down_sync(0xffffffffu, s, o);
        if (lane == 0) {
            if      (w == 0) out[SCAL_OFF+0] = s / 16384.f;                 // loss_po
            else if (w == 1) out[SCAL_OFF+1] = s / 16384.f;                 // loss_tr
            else if (w == 2) out[SCAL_OFF+4] = s / (16384.f*3.f);           // sindy_z
            else if (w == 3) out[SCAL_OFF+2] = s / (16384.f*2048.f);        // recon
            else if (w == 4) out[SCAL_OFF+3] = s / (16384.f*2048.f);        // sindy_x
            else             out[SCAL_OFF+5] = s / 21.f;                    // l1
        }
    }
}

// ================= launch =================
extern "C" void kernel_launch(void* const* d_in, const int* in_sizes, int n_in,
                              void* d_out, int out_size) {
    const float* x         = (const float*)d_in[0];
    const float* x_dot     = (const float*)d_in[1];
    const float* treatment = (const float*)d_in[2];
    const float* size_     = (const float*)d_in[3];
    const float* eW1 = (const float*)d_in[4];  const float* eb1 = (const float*)d_in[5];
    const float* eW2 = (const float*)d_in[6];  const float* eb2 = (const float*)d_in[7];
    const float* eW3 = (const float*)d_in[8];  const float* eb3 = (const float*)d_in[9];
    const float* eW4 = (const float*)d_in[10]; const float* eb4 = (const float*)d_in[11];
    const float* dW1 = (const float*)d_in[12]; const float* db1 = (const float*)d_in[13];
    const float* dW2 = (const float*)d_in[14]; const float* db2 = (const float*)d_in[15];
    const float* dW3 = (const float*)d_in[16]; const float* db3 = (const float*)d_in[17];
    const float* dW4 = (const float*)d_in[18]; const float* db4 = (const float*)d_in[19];
    const float* coef = (const float*)d_in[20];
    float* out = (float*)d_out;

    cudaFuncSetAttribute(k1_gemm, cudaFuncAttributeMaxDynamicSharedMemorySize, K1_SMEM);
    cudaFuncSetAttribute(k3_gemm, cudaFuncAttributeMaxDynamicSharedMemorySize, K3_SMEM);
    cudaFuncSetAttribute(k2_chain, cudaFuncAttributeMaxDynamicSharedMemorySize, K2_SMEM);

    k0_prep<<<1024, 256>>>(eW1, dW4);
    k1_gemm<<<dim3(128, 2), 256, K1_SMEM>>>(x, x_dot);
    k2_chain<<<256, 256, K2_SMEM>>>(treatment, size_, eW1, eb1, eW2, eb2, eW3, eb3,
                                    eW4, eb4, dW1, db1, dW2, db2, dW3, db3, coef, out);
    k3_gemm<<<dim3(16, 128, 2), 256, K3_SMEM>>>(db4, x, x_dot, out);
    k4_final<<<1, 512>>>(coef, out);
}

// round 17
// speedup vs baseline: 1.2341x; 1.0106x over previous
#include <cuda_runtime.h>
#include <cuda_fp16.h>
#include <mma.h>
#include <cstdint>

using namespace nvcuda;

#define B_SZ   16384
#define DIN    2048
#define XHAT_OFF (16384L*3)
#define SCAL_OFF (16384L*3 + 16384L*2048)

// k1: M=128 tile, single-pass fp16 (Ah, Bh only)
#define TS2 40                       // fp16 smem row stride (80B)
#define STAGE_H (128*TS2)
#define K1_SMEM (2*2*STAGE_H*2)      // 40960 B

// k3 (champion): M=128 one-shot layout; mid region = stage scratch
#define TS3 136                      // fp16 row stride (272B)
#define K3_T (128*TS3)               // halves per array
#define K3_SMEM (3*K3_T*2)           // 104448 B -> 2 CTAs/SM
#define K3_XB_OFF (2*K3_T*2)         // X double buffer over Bh region (post-MMA)

// ---------------- scratch (device globals) ----------------
__device__ float g_prea[B_SZ*128];
__device__ float g_pred[B_SZ*128];
__device__ __align__(256) __half g_h3h[B_SZ*128];
__device__ __align__(256) __half g_d3h[B_SZ*128];
__device__ __align__(256) __half g_eW1h[128*2048];
__device__ __align__(256) __half g_dW4h[2048*128];
__device__ float g_part_po[256], g_part_tr[256], g_part_sz[256];
__device__ float g_part_rec[2048], g_part_sx[2048];

__device__ __forceinline__ unsigned pkh(__half a, __half b) {
    __half2 t = __halves2half2(a, b);
    return *reinterpret_cast<unsigned*>(&t);
}
__device__ __forceinline__ void cpa16(void* sdst, const void* gsrc) {
    unsigned s = (unsigned)__cvta_generic_to_shared(sdst);
    asm volatile("cp.async.cg.shared.global [%0], [%1], 16;\n" :: "r"(s), "l"(gsrc));
}
__device__ __forceinline__ void cp_commit() { asm volatile("cp.async.commit_group;\n"); }
__device__ __forceinline__ void cp_wait1() { asm volatile("cp.async.wait_group 1;\n"); }
__device__ __forceinline__ void cp_wait0() { asm volatile("cp.async.wait_group 0;\n"); }

// ================= K0 =================
__global__ void __launch_bounds__(256) k0_prep(const float* __restrict__ eW1,
                                               const float* __restrict__ dW4) {
    int i = blockIdx.x * 256 + threadIdx.x;
    if (i < 128*2048) {
        int n = i >> 11, k = i & 2047;
        g_eW1h[i] = __float2half(eW1[n*2049 + k]);
    }
    if (i < 2048*128) {
        g_dW4h[i] = __float2half(dW4[i]);
    }
}

// ================= K1: GEMM fp16 1-pass, pipelined, single barrier per chunk ====
__global__ void __launch_bounds__(256, 2) k1_gemm(
    const float* __restrict__ x, const float* __restrict__ x_dot)
{
    extern __shared__ __half smb[];
    const int path = blockIdx.y;
    const float* A = (path == 0) ? x : x_dot;
    float* Out = (path == 0) ? g_prea : g_pred;
    const int m0 = blockIdx.x * 128;
    const int tid = threadIdx.x;
    const int w  = tid >> 5;
    const int wr = w >> 2;
    const int wc = w & 3;

    const float4* Asrc = reinterpret_cast<const float4*>(A);
    const uint4*  Bhg  = reinterpret_cast<const uint4*>(g_eW1h);

    const int ar  = tid >> 3;
    const int ac4 = tid & 7;
    const int br  = tid >> 2;
    const int bgc = tid & 3;

    wmma::fragment<wmma::accumulator,16,16,16,float> acc[4][2];
    #pragma unroll
    for (int i=0;i<4;i++)
        #pragma unroll
        for(int j=0;j<2;j++) wmma::fill_fragment(acc[i][j], 0.0f);

    float4 areg[4];
    #pragma unroll
    for (int i=0;i<4;i++)
        areg[i] = Asrc[(long)(m0 + ar + 32*i)*512 + ac4];
    {
        __half* Bh = smb + STAGE_H;
        #pragma unroll
        for (int i=0;i<2;i++) {
            int r = br + 64*i;
            cpa16(&Bh[r*TS2 + bgc*8], &Bhg[r*256 + bgc]);
        }
        cp_commit();
        __half* Ah = smb;
        #pragma unroll
        for (int i=0;i<4;i++) {
            int r = ar + 32*i;
            float4 v = areg[i];
            unsigned* ph = reinterpret_cast<unsigned*>(&Ah[r*TS2 + ac4*4]);
            ph[0]=pkh(__float2half(v.x), __float2half(v.y));
            ph[1]=pkh(__float2half(v.z), __float2half(v.w));
        }
    }

    #pragma unroll 1
    for (int c = 0; c < 64; c++) {
        const int s  = c & 1;
        const int sn = s ^ 1;
        if (c < 63) {
            #pragma unroll
            for (int i=0;i<4;i++)
                areg[i] = Asrc[(long)(m0 + ar + 32*i)*512 + (c+1)*8 + ac4];
            __half* Bh = smb + sn*2*STAGE_H + STAGE_H;
            #pragma unroll
            for (int i=0;i<2;i++) {
                int r = br + 64*i;
                cpa16(&Bh[r*TS2 + bgc*8], &Bhg[r*256 + (c+1)*4 + bgc]);
            }
            cp_commit();
            cp_wait1();
        } else {
            cp_wait0();
        }
        __syncthreads();
        {
            __half* Ah = smb + s*2*STAGE_H;
            __half* Bh = Ah + STAGE_H;
            #pragma unroll
            for (int kk = 0; kk < 32; kk += 16) {
                wmma::fragment<wmma::matrix_b,16,16,16,__half,wmma::col_major> bh[2];
                #pragma unroll
                for (int j=0;j<2;j++)
                    wmma::load_matrix_sync(bh[j], &Bh[(wc*32 + j*16)*TS2 + kk], TS2);
                #pragma unroll
                for (int i=0;i<4;i++) {
                    wmma::fragment<wmma::matrix_a,16,16,16,__half,wmma::row_major> ah;
                    wmma::load_matrix_sync(ah, &Ah[(wr*64 + i*16)*TS2 + kk], TS2);
                    #pragma unroll
                    for (int j=0;j<2;j++)
                        wmma::mma_sync(acc[i][j], ah, bh[j], acc[i][j]);
                }
            }
        }
        // NOTE: no barrier here. STS below targets stage sn's A region, last READ
        // in iteration c-1's MMA — every thread already passed this iteration's
        // barrier (post-dates all c-1 MMA). Concurrent MMA reads stage s (disjoint);
        // in-flight cp.async writes sn's B array (disjoint). Next iteration's
        // barrier orders these stores before their consumers.
        if (c < 63) {
            __half* Ah = smb + sn*2*STAGE_H;
            #pragma unroll
            for (int i=0;i<4;i++) {
                int r = ar + 32*i;
                float4 v = areg[i];
                unsigned* ph = reinterpret_cast<unsigned*>(&Ah[r*TS2 + ac4*4]);
                ph[0]=pkh(__float2half(v.x), __float2half(v.y));
                ph[1]=pkh(__float2half(v.z), __float2half(v.w));
            }
        }
    }
    #pragma unroll
    for (int i=0;i<4;i++)
        #pragma unroll
        for (int j=0;j<2;j++) {
            float* p = Out + (long)(m0 + wr*64 + i*16)*128 + wc*32 + j*16;
            wmma::store_matrix_sync(p, acc[i][j], 128, wmma::mem_row_major);
        }
}

// ================= K2: fused middle chain, 64 rows/CTA, single wave =========
#define W2T_OFF   0
#define W3T_OFF   (W2T_OFF + 128*64)
#define W4S_OFF   (W3T_OFF + 64*32)
#define DW1T_OFF  (W4S_OFF + 96)
#define DW2T_OFF  (DW1T_OFF + 96)
#define DW3T_OFF  (DW2T_OFF + 32*64)
#define EB1_OFF   (DW3T_OFF + 64*128)
#define EB2_OFF   (EB1_OFF + 128)
#define EB3_OFF   (EB2_OFF + 64)
#define EB4_OFF   (EB3_OFF + 32)
#define DB1_OFF   (EB4_OFF + 4)
#define DB2_OFF   (DB1_OFF + 32)
#define DB3_OFF   (DB2_OFF + 64)
#define W1L_OFF   (DB3_OFF + 128)
#define COEF_OFF  (W1L_OFF + 128)
#define BUF_OFF   (COEF_OFF + 26)
#define LRED_OFF  (BUF_OFF + 8*256)
#define K2_FLOATS (LRED_OFF + 24)
#define K2_SMEM   (K2_FLOATS * 4)

__device__ __forceinline__ float sigf(float x) { return 1.f/(1.f+__expf(-x)); }

__global__ void __launch_bounds__(256) k2_chain(
    const float* __restrict__ treatment, const float* __restrict__ size_,
    const float* __restrict__ eW1, const float* __restrict__ eb1,
    const float* __restrict__ eW2, const float* __restrict__ eb2,
    const float* __restrict__ eW3, const float* __restrict__ eb3,
    const float* __restrict__ eW4, const float* __restrict__ eb4,
    const float* __restrict__ dW1, const float* __restrict__ db1,
    const float* __restrict__ dW2, const float* __restrict__ db2,
    const float* __restrict__ dW3, const float* __restrict__ db3,
    const float* __restrict__ coef,
    float* __restrict__ out)
{
    extern __shared__ float sm[];
    const int tid = threadIdx.x;

    for (int i = tid; i < 64*128; i += 256) { int n=i>>7, k=i&127; sm[W2T_OFF + k*64 + n] = eW2[i]; }
    for (int i = tid; i < 32*64;  i += 256) { int n=i>>6, k=i&63;  sm[W3T_OFF + k*32 + n] = eW3[i]; }
    for (int i = tid; i < 3*32;   i += 256) sm[W4S_OFF + i] = eW4[i];
    for (int i = tid; i < 32*3;   i += 256) { int n=i/3,  k=i%3;  sm[DW1T_OFF + k*32 + n] = dW1[i]; }
    for (int i = tid; i < 64*32;  i += 256) { int n=i>>5, k=i&31; sm[DW2T_OFF + k*64 + n] = dW2[i]; }
    for (int i = tid; i < 128*64; i += 256) { int n=i>>6, k=i&63; sm[DW3T_OFF + k*128 + n] = dW3[i]; }
    if (tid < 128) sm[EB1_OFF+tid] = eb1[tid];
    if (tid < 64)  sm[EB2_OFF+tid] = eb2[tid];
    if (tid < 32)  sm[EB3_OFF+tid] = eb3[tid];
    if (tid < 3)   sm[EB4_OFF+tid] = eb4[tid];
    if (tid < 32)  sm[DB1_OFF+tid] = db1[tid];
    if (tid < 64)  sm[DB2_OFF+tid] = db2[tid];
    if (tid < 128) sm[DB3_OFF+tid] = db3[tid];
    if (tid < 128) sm[W1L_OFF+tid] = eW1[tid*2049 + 2048];
    if (tid < 21)  sm[COEF_OFF+tid] = coef[tid];
    __syncthreads();

    const int w = tid >> 5, lane = tid & 31;
    float2* pbuf = reinterpret_cast<float2*>(sm + BUF_OFF + w*256);
    float po = 0.f, tr = 0.f, szl = 0.f;

    for (int rr = 0; rr < 8; rr++) {
        const int row = (blockIdx.x*8 + w)*8 + rr;
        const float tre = treatment[row];

        #pragma unroll
        for (int jj=0;jj<4;jj++) {
            int n = lane + 32*jj;
            float add = tre * sm[W1L_OFF+n];
            float a1  = sigf(g_prea[(long)row*128+n] + add + sm[EB1_OFF+n]);
            float pd  = g_pred[(long)row*128+n] + add;
            pbuf[n] = make_float2(a1, a1*(1.f-a1)*pd);
        }
        __syncwarp();
        float a2v[2], d2v[2];
        #pragma unroll
        for (int jj=0;jj<2;jj++) {
            int n = lane + 32*jj;
            float s1 = sm[EB2_OFF+n], s2 = 0.f;
            #pragma unroll 8
            for (int k=0;k<128;k++) {
                float wv = sm[W2T_OFF + k*64 + n];
                float2 ad = pbuf[k];
                s1 = fmaf(ad.x, wv, s1);
                s2 = fmaf(ad.y, wv, s2);
            }
            float a = sigf(s1);
            a2v[jj] = a; d2v[jj] = a*(1.f-a)*s2;
        }
        __syncwarp();
        pbuf[lane]    = make_float2(a2v[0], d2v[0]);
        pbuf[lane+32] = make_float2(a2v[1], d2v[1]);
        __syncwarp();
        {
            float s1 = sm[EB3_OFF+lane], s2 = 0.f;
            #pragma unroll 8
            for (int k=0;k<64;k++) {
                float wv = sm[W3T_OFF + k*32 + lane];
                float2 ad = pbuf[k];
                s1 = fmaf(ad.x, wv, s1);
                s2 = fmaf(ad.y, wv, s2);
            }
            float a = sigf(s1);
            float d = a*(1.f-a)*s2;
            __syncwarp();
            pbuf[lane] = make_float2(a, d);
        }
        __syncwarp();
        float zz[3], zt[3];
        #pragma unroll
        for (int j=0;j<3;j++) {
            float s1 = sm[EB4_OFF+j], s2 = 0.f;
            #pragma unroll
            for (int k=0;k<32;k++) {
                float wv = sm[W4S_OFF + j*32 + k];
                float2 ad = pbuf[k];
                s1 = fmaf(ad.x, wv, s1);
                s2 = fmaf(ad.y, wv, s2);
            }
            zz[j]=s1; zt[j]=s2;
        }
        const float s = zz[0], d = zz[1], t3 = zz[2];
        float th[7] = {1.f, s, s*s, s*d, s*t3, s*s*d, s*s*t3};
        float zp[3] = {0.f,0.f,0.f};
        #pragma unroll
        for (int i=0;i<7;i++) {
            zp[0] = fmaf(th[i], sm[COEF_OFF+i*3+0], zp[0]);
            zp[1] = fmaf(th[i], sm[COEF_OFF+i*3+1], zp[1]);
            zp[2] = fmaf(th[i], sm[COEF_OFF+i*3+2], zp[2]);
        }
        if (lane == 0) {
            float dpo = s - size_[row];
            po += dpo*dpo;
            float l = t3;
            tr += fmaxf(l, 0.f) + log1pf(expf(-fabsf(l))) - l*tre;
            float e0 = zt[0]-zp[0], e1 = zt[1]-zp[1], e2 = zt[2]-zp[2];
            szl += e0*e0 + e1*e1 + e2*e2;
        }
        if (lane < 3) out[(long)row*3 + lane] = zz[lane];
        __syncwarp();
        {
            float w0 = sm[DW1T_OFF + 0*32 + lane];
            float w1 = sm[DW1T_OFF + 1*32 + lane];
            float w2 = sm[DW1T_OFF + 2*32 + lane];
            float h  = sigf(sm[DB1_OFF+lane] + s*w0 + d*w1 + t3*w2);
            float pd = zp[0]*w0 + zp[1]*w1 + zp[2]*w2;
            pbuf[lane] = make_float2(h, h*(1.f-h)*pd);
        }
        __syncwarp();
        float h2v[2], dd2v[2];
        #pragma unroll
        for (int jj=0;jj<2;jj++) {
            int n = lane + 32*jj;
            float s1 = sm[DB2_OFF+n], s2 = 0.f;
            #pragma unroll
            for (int k=0;k<32;k++) {
                float wv = sm[DW2T_OFF + k*64 + n];
                float2 ad = pbuf[k];
                s1 = fmaf(ad.x, wv, s1);
                s2 = fmaf(ad.y, wv, s2);
            }
            float h = sigf(s1);
            h2v[jj]=h; dd2v[jj]=h*(1.f-h)*s2;
        }
        __syncwarp();
        pbuf[lane]    = make_float2(h2v[0], dd2v[0]);
        pbuf[lane+32] = make_float2(h2v[1], dd2v[1]);
        __syncwarp();
        #pragma unroll
        for (int jj=0;jj<4;jj++) {
            int n = lane + 32*jj;
            float s1 = sm[DB3_OFF+n], s2 = 0.f;
            #pragma unroll 8
            for (int k=0;k<64;k++) {
                float wv = sm[DW3T_OFF + k*128 + n];
                float2 ad = pbuf[k];
                s1 = fmaf(ad.x, wv, s1);
                s2 = fmaf(ad.y, wv, s2);
            }
            float h = sigf(s1);
            float hd = h*(1.f-h)*s2;
            long idx = (long)row*128 + n;
            g_h3h[idx] = __float2half(h);
            g_d3h[idx] = __float2half(hd);
        }
        __syncwarp();
    }
    if (lane == 0) {
        sm[LRED_OFF + w]      = po;
        sm[LRED_OFF + 8 + w]  = tr;
        sm[LRED_OFF + 16 + w] = szl;
    }
    __syncthreads();
    if (tid == 0) {
        float a=0.f,b=0.f,c=0.f;
        for (int i=0;i<8;i++){ a+=sm[LRED_OFF+i]; b+=sm[LRED_OFF+8+i]; c+=sm[LRED_OFF+16+i]; }
        g_part_po[blockIdx.x]=a; g_part_tr[blockIdx.x]=b; g_part_sz[blockIdx.x]=c;
    }
}

// ================= K3 (champion): 1-pass one-shot GEMM + prefetched epilogue ====
__global__ void __launch_bounds__(256, 2) k3_gemm(
    const float* __restrict__ db4,
    const float* __restrict__ x, const float* __restrict__ x_dot,
    float* __restrict__ out)
{
    extern __shared__ __half smb[];
    char* smc = reinterpret_cast<char*>(smb);
    __half* Ah = smb;
    __half* Bh = smb + 2*K3_T;
    float* stgf = reinterpret_cast<float*>(smb);
    float* XB[2] = { reinterpret_cast<float*>(smc + K3_XB_OFF),
                     reinterpret_cast<float*>(smc + K3_XB_OFF + 16384) };

    const int path = blockIdx.z;
    const __half* Asrc = (path == 0) ? g_h3h : g_d3h;
    const float* Xs = (path == 0) ? x : x_dot;
    const int m0 = blockIdx.y * 128;
    const int n0 = blockIdx.x * 128;
    const int tid = threadIdx.x;
    const int w  = tid >> 5;
    const int lane = tid & 31;
    const int wr = w >> 2;
    const int wc = w & 3;

    {
        const uint4* Ah4 = reinterpret_cast<const uint4*>(Asrc + (long)m0*128);
        const uint4* Bh4 = reinterpret_cast<const uint4*>(g_dW4h + (long)n0*128);
        const int r  = tid >> 1;
        const int q0 = (tid & 1) * 8;
        #pragma unroll
        for (int qq = 0; qq < 8; qq++) {
            int q = q0 + qq;
            cpa16(&Ah[r*TS3 + q*8], &Ah4[r*16 + q]);
            cpa16(&Bh[r*TS3 + q*8], &Bh4[r*16 + q]);
        }
        cp_commit(); cp_wait0();
    }
    __syncthreads();

    wmma::fragment<wmma::accumulator,16,16,16,float> acc[4][2];
    #pragma unroll
    for (int i=0;i<4;i++)
        #pragma unroll
        for(int j=0;j<2;j++) wmma::fill_fragment(acc[i][j], 0.0f);

    #pragma unroll
    for (int kk = 0; kk < 128; kk += 16) {
        wmma::fragment<wmma::matrix_b,16,16,16,__half,wmma::col_major> bh[2];
        #pragma unroll
        for (int j=0;j<2;j++)
            wmma::load_matrix_sync(bh[j], &Bh[(wc*32 + j*16)*TS3 + kk], TS3);
        #pragma unroll
        for (int i=0;i<4;i++) {
            wmma::fragment<wmma::matrix_a,16,16,16,__half,wmma::row_major> ah;
            wmma::load_matrix_sync(ah, &Ah[(wr*64 + i*16)*TS3 + kk], TS3);
            #pragma unroll
            for (int j=0;j<2;j++)
                wmma::mma_sync(acc[i][j], ah, bh[j], acc[i][j]);
        }
    }
    __syncthreads();

    {
        const int r = tid >> 3, q = tid & 7;
        #pragma unroll
        for (int ii = 0; ii < 4; ii++) {
            int rr = r + 32*ii;
            cpa16(&XB[0][rr*32 + q*4], &Xs[(long)(m0+rr)*2048 + n0 + 0*32 + q*4]);
        }
        cp_commit();
        #pragma unroll
        for (int i=0;i<4;i++)
            #pragma unroll
            for (int j=0;j<2;j++)
                wmma::store_matrix_sync(&stgf[(wr*64 + i*16)*132 + wc*32 + j*16],
                                        acc[i][j], 132, wmma::mem_row_major);
        #pragma unroll
        for (int ii = 0; ii < 4; ii++) {
            int rr = r + 32*ii;
            cpa16(&XB[1][rr*32 + q*4], &Xs[(long)(m0+rr)*2048 + n0 + 1*32 + q*4]);
        }
        cp_commit();
    }

    float lacc = 0.f;
    #pragma unroll 1
    for (int ch = 0; ch < 4; ch++) {
        if (ch < 3) cp_wait1(); else cp_wait0();
        __syncthreads();
        const float* xb = XB[ch & 1];
        const int cg = n0 + ch*32 + lane;
        const float db4v = (path == 0) ? db4[cg] : 0.f;
        #pragma unroll
        for (int i = 0; i < 16; i++) {
            int rloc = w*16 + i;
            float v = stgf[rloc*132 + ch*32 + lane];
            if (path == 0) {
                v += db4v;
                out[XHAT_OFF + (long)(m0+rloc)*2048 + cg] = v;
            }
            float df = v - xb[rloc*32 + lane];
            lacc += df*df;
        }
        if (ch < 2) {
            __syncthreads();
            const int r = tid >> 3, q = tid & 7;
            #pragma unroll
            for (int ii = 0; ii < 4; ii++) {
                int rr = r + 32*ii;
                cpa16(&XB[ch & 1][rr*32 + q*4],
                      &Xs[(long)(m0+rr)*2048 + n0 + (ch+2)*32 + q*4]);
            }
            cp_commit();
        }
    }

    __shared__ float wred[8];
    #pragma unroll
    for (int o = 16; o > 0; o >>= 1) lacc += __shfl_down_sync(0xffffffffu, lacc, o);
    if (lane == 0) wred[w] = lacc;
    __syncthreads();
    if (tid == 0) {
        float t = 0.f;
        #pragma unroll
        for (int i=0;i<8;i++) t += wred[i];
        int idx = blockIdx.y*16 + blockIdx.x;
        if (path == 0) g_part_rec[idx] = t;
        else           g_part_sx[idx]  = t;
    }
}

// ================= K4: parallel deterministic finalize (512 threads) ==========
__global__ void __launch_bounds__(512) k4_final(const float* __restrict__ coef,
                                                float* __restrict__ out) {
    __shared__ float part[6][16];
    const int tid = threadIdx.x, w = tid >> 5, lane = tid & 31;
    float v[6];
    v[0] = (tid < 256) ? g_part_po[tid] : 0.f;
    v[1] = (tid < 256) ? g_part_tr[tid] : 0.f;
    v[2] = (tid < 256) ? g_part_sz[tid] : 0.f;
    v[3] = g_part_rec[tid] + g_part_rec[tid+512] + g_part_rec[tid+1024] + g_part_rec[tid+1536];
    v[4] = g_part_sx[tid]  + g_part_sx[tid+512]  + g_part_sx[tid+1024]  + g_part_sx[tid+1536];
    v[5] = (tid < 21) ? fabsf(coef[tid]) : 0.f;
    #pragma unroll
    for (int j = 0; j < 6; j++) {
        float s = v[j];
        #pragma unroll
        for (int o = 16; o > 0; o >>= 1) s += __shfl_down_sync(0xffffffffu, s, o);
        if (lane == 0) part[j][w] = s;
    }
    __syncthreads();
    if (w < 6) {
        float s = (lane < 16) ? part[w][lane] : 0.f;
        #pragma unroll
        for (int o = 8; o > 0; o >>= 1) s += __shfl_down_sync(0xffffffffu, s, o);
        if (lane == 0) {
            if      (w == 0) out[SCAL_OFF+0] = s / 16384.f;                 // loss_po
            else if (w == 1) out[SCAL_OFF+1] = s / 16384.f;                 // loss_tr
            else if (w == 2) out[SCAL_OFF+4] = s / (16384.f*3.f);           // sindy_z
            else if (w == 3) out[SCAL_OFF+2] = s / (16384.f*2048.f);        // recon
            else if (w == 4) out[SCAL_OFF+3] = s / (16384.f*2048.f);        // sindy_x
            else             out[SCAL_OFF+5] = s / 21.f;                    // l1
        }
    }
}

// ================= launch =================
extern "C" void kernel_launch(void* const* d_in, const int* in_sizes, int n_in,
                              void* d_out, int out_size) {
    const float* x         = (const float*)d_in[0];
    const float* x_dot     = (const float*)d_in[1];
    const float* treatment = (const float*)d_in[2];
    const float* size_     = (const float*)d_in[3];
    const float* eW1 = (const float*)d_in[4];  const float* eb1 = (const float*)d_in[5];
    const float* eW2 = (const float*)d_in[6];  const float* eb2 = (const float*)d_in[7];
    const float* eW3 = (const float*)d_in[8];  const float* eb3 = (const float*)d_in[9];
    const float* eW4 = (const float*)d_in[10]; const float* eb4 = (const float*)d_in[11];
    const float* dW1 = (const float*)d_in[12]; const float* db1 = (const float*)d_in[13];
    const float* dW2 = (const float*)d_in[14]; const float* db2 = (const float*)d_in[15];
    const float* dW3 = (const float*)d_in[16]; const float* db3 = (const float*)d_in[17];
    const float* dW4 = (const float*)d_in[18]; const float* db4 = (const float*)d_in[19];
    const float* coef = (const float*)d_in[20];
    float* out = (float*)d_out;

    cudaFuncSetAttribute(k1_gemm, cudaFuncAttributeMaxDynamicSharedMemorySize, K1_SMEM);
    cudaFuncSetAttribute(k3_gemm, cudaFuncAttributeMaxDynamicSharedMemorySize, K3_SMEM);
    cudaFuncSetAttribute(k2_chain, cudaFuncAttributeMaxDynamicSharedMemorySize, K2_SMEM);

    k0_prep<<<1024, 256>>>(eW1, dW4);
    k1_gemm<<<dim3(128, 2), 256, K1_SMEM>>>(x, x_dot);
    k2_chain<<<256, 256, K2_SMEM>>>(treatment, size_, eW1, eb1, eW2, eb2, eW3, eb3,
                                    eW4, eb4, dW1, db1, dW2, db2, dW3, db3, coef, out);
    k3_gemm<<<dim3(16, 128, 2), 256, K3_SMEM>>>(db4, x, x_dot, out);
    k4_final<<<1, 512>>>(coef, out);
}